// round 1
// baseline (speedup 1.0000x reference)
#include <cuda_runtime.h>
#include <cstdint>

// ---------------------------------------------------------------------------
// Swin-style windowed attention block, 131072 tokens, D=256, FF=1024.
// Round 1: multi-kernel pipeline, tf32 mma.sync GEMMs (rna-rounded), fp32
// attention/LN. Scratch in __device__ globals (no allocs).
// ---------------------------------------------------------------------------

#define M_TOK  131072
#define DMODEL 256
#define DQK    64
#define DFF    1024
#define NWIN   8192

// ----------------------------- scratch -------------------------------------
__device__ float g_xg[M_TOK * DMODEL];   // gathered x (window token order)
__device__ float g_q [M_TOK * DQK];
__device__ float g_k [M_TOK * DQK];
__device__ float g_v [M_TOK * DMODEL];
__device__ float g_o [M_TOK * DMODEL];   // attention output
__device__ float g_u [M_TOK * DMODEL];   // o @ Wo + bo
__device__ float g_h [M_TOK * DMODEL];   // LN1 output
__device__ float g_f [M_TOK * DFF];      // relu(h@W1+bf1)
__device__ float g_g [M_TOK * DMODEL];   // f@W2+bf2

// token m (window order) -> row index in original [B*R*C] layout
__device__ __forceinline__ int src_row(int m) {
    int t  = m & 15;          // token within window
    int w  = m >> 4;          // window id
    int wj = t & 3, wi = t >> 2;
    int sj = w & 31, si = (w >> 5) & 31, b = w >> 10;
    return ((b * 128) + si * 4 + wi) * 128 + sj * 4 + wj;
}

// ----------------------------- gather --------------------------------------
__global__ void gather_kernel(const float* __restrict__ x, float* __restrict__ xg) {
    const float4* x4  = reinterpret_cast<const float4*>(x);
    float4*       xg4 = reinterpret_cast<float4*>(xg);
    int base = blockIdx.x * 1024 + threadIdx.x;
    #pragma unroll
    for (int i = 0; i < 4; i++) {
        int idx = base + i * 256;            // float4 index
        int m = idx >> 6;                    // 64 float4 per row
        int c = idx & 63;
        xg4[idx] = x4[src_row(m) * 64 + c];
    }
}

// ----------------------------- tf32 GEMM -----------------------------------
__device__ __forceinline__ uint32_t f2tf32(float f) {
    uint32_t u;
    asm("cvt.rna.tf32.f32 %0, %1;" : "=r"(u) : "f"(f));
    return u;
}

__device__ __forceinline__ void mma_tf32(float* c, const uint32_t* a, const uint32_t* b) {
    asm volatile(
        "mma.sync.aligned.m16n8k8.row.col.f32.tf32.tf32.f32 "
        "{%0,%1,%2,%3}, {%4,%5,%6,%7}, {%8,%9}, {%0,%1,%2,%3};\n"
        : "+f"(c[0]), "+f"(c[1]), "+f"(c[2]), "+f"(c[3])
        : "r"(a[0]), "r"(a[1]), "r"(a[2]), "r"(a[3]), "r"(b[0]), "r"(b[1]));
}

// C[M,N] = A[M,K] @ B[K,N] + bias (+relu). Row-major, K % 16 == 0, M % 128 == 0,
// N % 8 == 0. BM=BN=128, BK=16, 256 threads, warp grid 2x4, warp tile 64x32.
template <bool RELU>
__global__ void __launch_bounds__(256)
gemm_tf32(const float* __restrict__ A, const float* __restrict__ B,
          const float* __restrict__ bias, float* __restrict__ C,
          int M, int N, int K) {
    // A tile stored [m][k], stride 20 words (conflict-free frag loads).
    // B tile stored [k][n], stride 136 words.
    __shared__ __align__(16) uint32_t As[2][128 * 20];
    __shared__ __align__(16) uint32_t Bs[2][16 * 136];

    const int tid  = threadIdx.x;
    const int lane = tid & 31;
    const int warp = tid >> 5;
    const int wm   = warp >> 2;      // 0..1
    const int wn   = warp & 3;       // 0..3
    const int lq   = lane >> 2;      // 0..7
    const int lr   = lane & 3;       // 0..3
    const int row0 = blockIdx.y * 128;
    const int n0   = blockIdx.x * 128;

    float acc[4][4][4];
    #pragma unroll
    for (int mi = 0; mi < 4; mi++)
        #pragma unroll
        for (int ni = 0; ni < 4; ni++)
            #pragma unroll
            for (int j = 0; j < 4; j++) acc[mi][ni][j] = 0.f;

    const int arow = tid >> 2;            // 0..63
    const int acol = (tid & 3) << 2;      // 0,4,8,12
    const int brow = tid >> 5;            // 0..7
    const int bcol = (tid & 31) << 2;     // 0..124

    const int ktiles = K >> 4;
    float4 sa[2], sb[2];

    auto ldg = [&](int kt) {
        #pragma unroll
        for (int r = 0; r < 2; r++)
            sa[r] = *reinterpret_cast<const float4*>(
                A + (row0 + arow + r * 64) * K + kt * 16 + acol);
        int gc = n0 + bcol;
        #pragma unroll
        for (int r = 0; r < 2; r++) {
            if (gc < N)
                sb[r] = *reinterpret_cast<const float4*>(
                    B + (kt * 16 + brow + r * 8) * N + gc);
            else
                sb[r] = make_float4(0.f, 0.f, 0.f, 0.f);
        }
    };
    auto sts = [&](int buf) {
        #pragma unroll
        for (int r = 0; r < 2; r++) {
            uint4 u;
            u.x = f2tf32(sa[r].x); u.y = f2tf32(sa[r].y);
            u.z = f2tf32(sa[r].z); u.w = f2tf32(sa[r].w);
            *reinterpret_cast<uint4*>(&As[buf][(arow + r * 64) * 20 + acol]) = u;
        }
        #pragma unroll
        for (int r = 0; r < 2; r++) {
            uint4 u;
            u.x = f2tf32(sb[r].x); u.y = f2tf32(sb[r].y);
            u.z = f2tf32(sb[r].z); u.w = f2tf32(sb[r].w);
            *reinterpret_cast<uint4*>(&Bs[buf][(brow + r * 8) * 136 + bcol]) = u;
        }
    };
    auto compute = [&](int buf) {
        #pragma unroll
        for (int ks = 0; ks < 2; ks++) {
            const int k8 = ks * 8;
            uint32_t af[4][4], bf[4][2];
            #pragma unroll
            for (int mi = 0; mi < 4; mi++) {
                int mb = wm * 64 + mi * 16 + lq;
                af[mi][0] = As[buf][ mb      * 20 + k8 + lr];
                af[mi][1] = As[buf][(mb + 8) * 20 + k8 + lr];
                af[mi][2] = As[buf][ mb      * 20 + k8 + lr + 4];
                af[mi][3] = As[buf][(mb + 8) * 20 + k8 + lr + 4];
            }
            #pragma unroll
            for (int ni = 0; ni < 4; ni++) {
                int nb = wn * 32 + ni * 8 + lq;
                bf[ni][0] = Bs[buf][(k8 + lr)     * 136 + nb];
                bf[ni][1] = Bs[buf][(k8 + lr + 4) * 136 + nb];
            }
            #pragma unroll
            for (int mi = 0; mi < 4; mi++)
                #pragma unroll
                for (int ni = 0; ni < 4; ni++)
                    mma_tf32(acc[mi][ni], af[mi], bf[ni]);
        }
    };

    ldg(0);
    sts(0);
    __syncthreads();
    for (int kt = 0; kt < ktiles; kt++) {
        int cur = kt & 1;
        if (kt + 1 < ktiles) ldg(kt + 1);
        compute(cur);
        if (kt + 1 < ktiles) sts(cur ^ 1);
        __syncthreads();
    }

    // epilogue: + bias (+relu)
    #pragma unroll
    for (int mi = 0; mi < 4; mi++) {
        #pragma unroll
        for (int ni = 0; ni < 4; ni++) {
            int r0 = row0 + wm * 64 + mi * 16 + lq;
            int c0 = n0 + wn * 32 + ni * 8 + 2 * lr;
            if (c0 < N) {
                float b0 = bias[c0], b1 = bias[c0 + 1];
                float v0 = acc[mi][ni][0] + b0;
                float v1 = acc[mi][ni][1] + b1;
                float v2 = acc[mi][ni][2] + b0;
                float v3 = acc[mi][ni][3] + b1;
                if (RELU) {
                    v0 = fmaxf(v0, 0.f); v1 = fmaxf(v1, 0.f);
                    v2 = fmaxf(v2, 0.f); v3 = fmaxf(v3, 0.f);
                }
                C[ r0      * N + c0    ] = v0;
                C[ r0      * N + c0 + 1] = v1;
                C[(r0 + 8) * N + c0    ] = v2;
                C[(r0 + 8) * N + c0 + 1] = v3;
            }
        }
    }
}

// --------------------------- attention (per window) -------------------------
__global__ void __launch_bounds__(256)
attn_kernel(const float* __restrict__ q, const float* __restrict__ k,
            const float* __restrict__ v, float* __restrict__ o) {
    __shared__ float qs[16 * 64];
    __shared__ float ks[16 * 64];
    __shared__ float vs[16 * 256];
    __shared__ float sc[16][17];

    const int w = blockIdx.x, t = threadIdx.x;
    const float* qb = q + w * (16 * 64);
    const float* kb = k + w * (16 * 64);
    const float* vb = v + w * (16 * 256);

    for (int i = t; i < 16 * 64; i += 256) { qs[i] = qb[i]; ks[i] = kb[i]; }
    for (int i = t; i < 16 * 256; i += 256) vs[i] = vb[i];
    __syncthreads();

    {   // one score per thread: 16x16 scores, dot over 64
        int qi = t >> 4, kj = t & 15;
        float s = 0.f;
        #pragma unroll
        for (int e = 0; e < 64; e++) s += qs[qi * 64 + e] * ks[kj * 64 + e];
        sc[qi][kj] = s * 0.125f;   // 1/sqrt(64)
    }
    __syncthreads();

    if (t < 16) {   // row softmax
        float mx = -1e30f;
        #pragma unroll
        for (int j = 0; j < 16; j++) mx = fmaxf(mx, sc[t][j]);
        float sum = 0.f;
        #pragma unroll
        for (int j = 0; j < 16; j++) { float e = __expf(sc[t][j] - mx); sc[t][j] = e; sum += e; }
        float inv = 1.f / sum;
        #pragma unroll
        for (int j = 0; j < 16; j++) sc[t][j] *= inv;
    }
    __syncthreads();

    {   // o = attn @ v : each thread 16 outputs of one token
        int tok = t >> 4;
        int ds  = (t & 15) * 16;
        float a[16];
        #pragma unroll
        for (int kk = 0; kk < 16; kk++) a[kk] = sc[tok][kk];
        float* ob = o + w * (16 * 256) + tok * 256 + ds;
        #pragma unroll
        for (int j = 0; j < 16; j++) {
            float s = 0.f;
            #pragma unroll
            for (int kk = 0; kk < 16; kk++) s += a[kk] * vs[kk * 256 + ds + j];
            ob[j] = s;
        }
    }
}

// --------------------------- LN(A + B) (+scatter) ---------------------------
template <bool SCATTER>
__global__ void __launch_bounds__(256)
ln_add_kernel(const float* __restrict__ A, const float* __restrict__ Bv,
              const float* __restrict__ gamma, const float* __restrict__ beta,
              float* __restrict__ out) {
    const int warp = threadIdx.x >> 5, lane = threadIdx.x & 31;
    const int row  = blockIdx.x * 8 + warp;
    const float* a = A  + row * DMODEL;
    const float* b = Bv + row * DMODEL;

    float vals[8];
    float s = 0.f, sq = 0.f;
    #pragma unroll
    for (int j = 0; j < 8; j++) {
        int d = lane + 32 * j;
        float v = a[d] + b[d];
        vals[j] = v; s += v; sq += v * v;
    }
    #pragma unroll
    for (int off = 16; off; off >>= 1) {
        s  += __shfl_xor_sync(0xffffffffu, s,  off);
        sq += __shfl_xor_sync(0xffffffffu, sq, off);
    }
    const float mean = s * (1.f / DMODEL);
    const float var  = sq * (1.f / DMODEL) - mean * mean;
    const float rstd = rsqrtf(var + 1e-5f);

    const int orow = SCATTER ? src_row(row) : row;
    float* op = out + orow * DMODEL;
    #pragma unroll
    for (int j = 0; j < 8; j++) {
        int d = lane + 32 * j;
        op[d] = (vals[j] - mean) * rstd * gamma[d] + beta[d];
    }
}

// ------------------------------ launch --------------------------------------
extern "C" void kernel_launch(void* const* d_in, const int* in_sizes, int n_in,
                              void* d_out, int out_size) {
    const float* x   = (const float*)d_in[0];
    const float* Wq  = (const float*)d_in[1];
    const float* bq  = (const float*)d_in[2];
    const float* Wk  = (const float*)d_in[3];
    const float* bk  = (const float*)d_in[4];
    const float* Wv  = (const float*)d_in[5];
    const float* bv  = (const float*)d_in[6];
    const float* Wo  = (const float*)d_in[7];
    const float* bo  = (const float*)d_in[8];
    const float* g1  = (const float*)d_in[9];
    const float* b1  = (const float*)d_in[10];
    const float* W1  = (const float*)d_in[11];
    const float* bf1 = (const float*)d_in[12];
    const float* W2  = (const float*)d_in[13];
    const float* bf2 = (const float*)d_in[14];
    const float* g2  = (const float*)d_in[15];
    const float* b2  = (const float*)d_in[16];
    float* out = (float*)d_out;

    void *pxg, *pq, *pk, *pv, *po, *pu, *ph, *pf, *pg;
    cudaGetSymbolAddress(&pxg, g_xg);
    cudaGetSymbolAddress(&pq,  g_q);
    cudaGetSymbolAddress(&pk,  g_k);
    cudaGetSymbolAddress(&pv,  g_v);
    cudaGetSymbolAddress(&po,  g_o);
    cudaGetSymbolAddress(&pu,  g_u);
    cudaGetSymbolAddress(&ph,  g_h);
    cudaGetSymbolAddress(&pf,  g_f);
    cudaGetSymbolAddress(&pg,  g_g);
    float* xg = (float*)pxg; float* q = (float*)pq; float* k = (float*)pk;
    float* v  = (float*)pv;  float* o = (float*)po; float* u = (float*)pu;
    float* h  = (float*)ph;  float* f = (float*)pf; float* gb = (float*)pg;

    const int MB = M_TOK / 128;   // 1024 m-blocks

    gather_kernel<<<NWIN, 256>>>(x, xg);

    gemm_tf32<false><<<dim3(1, MB), 256>>>(xg, Wq, bq, q, M_TOK, DQK,    DMODEL);
    gemm_tf32<false><<<dim3(1, MB), 256>>>(xg, Wk, bk, k, M_TOK, DQK,    DMODEL);
    gemm_tf32<false><<<dim3(2, MB), 256>>>(xg, Wv, bv, v, M_TOK, DMODEL, DMODEL);

    attn_kernel<<<NWIN, 256>>>(q, k, v, o);

    gemm_tf32<false><<<dim3(2, MB), 256>>>(o, Wo, bo, u, M_TOK, DMODEL, DMODEL);
    ln_add_kernel<false><<<M_TOK / 8, 256>>>(xg, u, g1, b1, h);

    gemm_tf32<true ><<<dim3(8, MB), 256>>>(h, W1, bf1, f,  M_TOK, DFF,    DMODEL);
    gemm_tf32<false><<<dim3(2, MB), 256>>>(f, W2, bf2, gb, M_TOK, DMODEL, DFF);

    ln_add_kernel<true><<<M_TOK / 8, 256>>>(h, gb, g2, b2, out);
}

// round 3
// speedup vs baseline: 1.2786x; 1.2786x over previous
#include <cuda_runtime.h>
#include <cstdint>

// ---------------------------------------------------------------------------
// Round 3: mma.sync tf32 GEMMs with cp.async 3-stage pipeline + ldmatrix
// fragment loads (tcgen05 unavailable: harness compiles for plain sm_103).
// All GEMM operands pre-rounded to tf32 so cp.async can copy raw bits.
// ---------------------------------------------------------------------------

#define M_TOK  131072
#define DMODEL 256
#define DQKV   384
#define DFF    1024
#define NWIN   8192

// ----------------------------- scratch -------------------------------------
__device__ float g_xg [(size_t)M_TOK * DMODEL];   // tf32(gathered x)
__device__ float g_qkv[(size_t)M_TOK * DQKV];
__device__ float g_o  [(size_t)M_TOK * DMODEL];
__device__ float g_u  [(size_t)M_TOK * DMODEL];
__device__ float g_h  [(size_t)M_TOK * DMODEL];
__device__ float g_f  [(size_t)M_TOK * DFF];
__device__ float g_gg [(size_t)M_TOK * DMODEL];
__device__ float g_bt_qkv[DQKV * DMODEL];   // [N][K] tf32-rounded
__device__ float g_bt_o [DMODEL * DMODEL];
__device__ float g_bt_1 [DFF * DMODEL];
__device__ float g_bt_2 [DMODEL * DFF];
__device__ float g_bqkv[DQKV];

__device__ __forceinline__ int src_row(int m) {
    int t  = m & 15;
    int w  = m >> 4;
    int wj = t & 3, wi = t >> 2;
    int sj = w & 31, si = (w >> 5) & 31, b = w >> 10;
    return ((b * 128) + si * 4 + wi) * 128 + sj * 4 + wj;
}

__device__ __forceinline__ float f2tf32(float f) {
    uint32_t u;
    asm("cvt.rna.tf32.f32 %0, %1;" : "=r"(u) : "f"(f));
    return __uint_as_float(u);
}

__device__ __forceinline__ uint32_t smem_u32(const void* p) {
    uint32_t a;
    asm("{ .reg .u64 t; cvta.to.shared.u64 t, %1; cvt.u32.u64 %0, t; }" : "=r"(a) : "l"(p));
    return a;
}
__device__ __forceinline__ void cp16(uint32_t s, const void* g) {
    asm volatile("cp.async.cg.shared.global [%0], [%1], 16;" :: "r"(s), "l"(g));
}
__device__ __forceinline__ void cp_commit() {
    asm volatile("cp.async.commit_group;" ::: "memory");
}
template <int N>
__device__ __forceinline__ void cp_wait() {
    asm volatile("cp.async.wait_group %0;" :: "n"(N) : "memory");
}
__device__ __forceinline__ void ldsm4(uint32_t& r0, uint32_t& r1, uint32_t& r2,
                                      uint32_t& r3, uint32_t addr) {
    asm volatile("ldmatrix.sync.aligned.m8n8.x4.shared.b16 {%0,%1,%2,%3}, [%4];"
                 : "=r"(r0), "=r"(r1), "=r"(r2), "=r"(r3) : "r"(addr));
}
__device__ __forceinline__ void mma_tf32(float* c, const uint32_t* a, const uint32_t* b) {
    asm volatile(
        "mma.sync.aligned.m16n8k8.row.col.f32.tf32.tf32.f32 "
        "{%0,%1,%2,%3}, {%4,%5,%6,%7}, {%8,%9}, {%0,%1,%2,%3};\n"
        : "+f"(c[0]), "+f"(c[1]), "+f"(c[2]), "+f"(c[3])
        : "r"(a[0]), "r"(a[1]), "r"(a[2]), "r"(a[3]), "r"(b[0]), "r"(b[1]));
}
__device__ __forceinline__ uint32_t swz(uint32_t b) { return b ^ ((b >> 3) & 0x70); }

// --------------------------- weight transpose --------------------------------
__global__ void wtrans(const float* __restrict__ W, float* __restrict__ Bt,
                       int K, int N, int nofs, int ldk) {
    int idx = blockIdx.x * 256 + threadIdx.x;
    if (idx >= K * N) return;
    int k = idx / N, n = idx % N;
    Bt[(size_t)(nofs + n) * ldk + k] = f2tf32(W[idx]);
}

// ----------------------------- gather + round --------------------------------
__global__ void gather_kernel(const float* __restrict__ x, float* __restrict__ xg) {
    const float4* x4  = reinterpret_cast<const float4*>(x);
    float4*       xg4 = reinterpret_cast<float4*>(xg);
    int base = blockIdx.x * 1024 + threadIdx.x;
    #pragma unroll
    for (int i = 0; i < 4; i++) {
        int idx = base + i * 256;
        int m = idx >> 6, c = idx & 63;
        float4 v = x4[src_row(m) * 64 + c];
        v.x = f2tf32(v.x); v.y = f2tf32(v.y); v.z = f2tf32(v.z); v.w = f2tf32(v.w);
        xg4[idx] = v;
    }
}

// ------------------------------- GEMM ----------------------------------------
// C[M,N] = A[M,K] @ Bt^T + bias (+relu)(+round). A,Bt pre-rounded tf32.
// BM=BN=128, BK=32, 3-stage cp.async, 256 thr, warp grid 2x4, warp tile 64x32.
#define ABYTES 16384
#define STG    32768
template <bool RELU, bool ROUND>
__global__ void __launch_bounds__(256, 2)
gemm_mma(const float* __restrict__ A, const float* __restrict__ Bt,
         const float* __restrict__ bias, float* __restrict__ C,
         int N, int K)
{
    extern __shared__ char smem[];
    const uint32_t sb = smem_u32(smem);

    const int tid  = threadIdx.x;
    const int lane = tid & 31, warp = tid >> 5;
    const int wm = warp >> 2, wn = warp & 3;
    const int lq = lane >> 2, lr = lane & 3;
    const int row0 = blockIdx.y * 128;
    const int n0   = blockIdx.x * 128;
    const int KT   = K >> 5;

    float acc[4][4][4];
    #pragma unroll
    for (int mi = 0; mi < 4; mi++)
        #pragma unroll
        for (int ni = 0; ni < 4; ni++)
            #pragma unroll
            for (int j = 0; j < 4; j++) acc[mi][ni][j] = 0.f;

    // cp.async mapping: 128 rows x 8 segs(16B); 256 thr x 4 iters
    const int r_ld = tid >> 3;        // 0..31, +32 per iter
    const int cseg = tid & 7;
    const size_t aRow0 = (size_t)(row0 + r_ld) * K;
    const size_t bRow0 = (size_t)(n0   + r_ld) * K;
    const uint32_t sOff = swz(r_ld * 128 + cseg * 16);

    auto load_stage = [&](int kt, int buf) {
        const int kofs = kt * 32 + cseg * 4;
        const uint32_t aBase = sb + buf * STG;
        const uint32_t bBase = aBase + ABYTES;
        #pragma unroll
        for (int i = 0; i < 4; i++) {
            // rows advance by 32: smem offset += 32*128 (swizzle unaffected: row&7 same)
            cp16(aBase + sOff + i * 4096, A  + aRow0 + (size_t)i * 32 * K + kofs);
            cp16(bBase + sOff + i * 4096, Bt + bRow0 + (size_t)i * 32 * K + kofs);
        }
        cp_commit();
    };

    // ldmatrix thread addressing
    const int quad = lane >> 3, r8 = lane & 7;
    const int aRowL = wm * 64 + (quad & 1) * 8 + r8;     // + mi*16
    const int aCsegL = quad >> 1;                         // + ks*2
    const int bRowL = wn * 32 + (quad >> 1) * 8 + r8;    // + nt*16
    const int bCsegL = quad & 1;                          // + ks*2

    auto compute = [&](int buf) {
        const uint32_t aBase = sb + buf * STG;
        const uint32_t bBase = aBase + ABYTES;
        #pragma unroll
        for (int ks = 0; ks < 4; ks++) {
            uint32_t af[4][4], bf[2][4];
            #pragma unroll
            for (int mi = 0; mi < 4; mi++) {
                int row = aRowL + mi * 16;
                uint32_t ad = aBase + swz(row * 128 + (ks * 2 + aCsegL) * 16);
                ldsm4(af[mi][0], af[mi][1], af[mi][2], af[mi][3], ad);
            }
            #pragma unroll
            for (int nt = 0; nt < 2; nt++) {
                int row = bRowL + nt * 16;
                uint32_t bd = bBase + swz(row * 128 + (ks * 2 + bCsegL) * 16);
                ldsm4(bf[nt][0], bf[nt][1], bf[nt][2], bf[nt][3], bd);
            }
            #pragma unroll
            for (int mi = 0; mi < 4; mi++) {
                #pragma unroll
                for (int nt = 0; nt < 2; nt++) {
                    mma_tf32(acc[mi][nt * 2 + 0], af[mi], &bf[nt][0]);
                    mma_tf32(acc[mi][nt * 2 + 1], af[mi], &bf[nt][2]);
                }
            }
        }
    };

    load_stage(0, 0);
    load_stage(1, 1);
    for (int kt = 0; kt < KT; kt++) {
        cp_wait<1>();
        __syncthreads();
        if (kt + 2 < KT) load_stage(kt + 2, (kt + 2) % 3);
        else cp_commit();
        compute(kt % 3);
    }

    // epilogue
    #pragma unroll
    for (int mi = 0; mi < 4; mi++) {
        #pragma unroll
        for (int ni = 0; ni < 4; ni++) {
            const int r0 = row0 + wm * 64 + mi * 16 + lq;
            const int c0 = n0 + wn * 32 + ni * 8 + 2 * lr;
            const float b0 = __ldg(bias + c0), b1 = __ldg(bias + c0 + 1);
            float v0 = acc[mi][ni][0] + b0;
            float v1 = acc[mi][ni][1] + b1;
            float v2 = acc[mi][ni][2] + b0;
            float v3 = acc[mi][ni][3] + b1;
            if (RELU) {
                v0 = fmaxf(v0, 0.f); v1 = fmaxf(v1, 0.f);
                v2 = fmaxf(v2, 0.f); v3 = fmaxf(v3, 0.f);
            }
            if (ROUND) {
                v0 = f2tf32(v0); v1 = f2tf32(v1);
                v2 = f2tf32(v2); v3 = f2tf32(v3);
            }
            *reinterpret_cast<float2*>(C + (size_t)r0 * N + c0)       = make_float2(v0, v1);
            *reinterpret_cast<float2*>(C + (size_t)(r0 + 8) * N + c0) = make_float2(v2, v3);
        }
    }
}

// --------------------------- attention (per window) -------------------------
__global__ void __launch_bounds__(256)
attn_kernel(const float* __restrict__ qkv, float* __restrict__ o) {
    __shared__ float qs[16 * 64];
    __shared__ float ks[16 * 64];
    __shared__ float vs[16 * 256];
    __shared__ float sc[16][17];

    const int w = blockIdx.x, t = threadIdx.x;
    const float* base = qkv + (size_t)w * 16 * DQKV;

    for (int i = t; i < 16 * 64; i += 256) {
        int r = i >> 6, c = i & 63;
        qs[i] = base[r * DQKV + c];
        ks[i] = base[r * DQKV + 64 + c];
    }
    for (int i = t; i < 16 * 256; i += 256) {
        int r = i >> 8, c = i & 255;
        vs[i] = base[r * DQKV + 128 + c];
    }
    __syncthreads();

    {
        int qi = t >> 4, kj = t & 15;
        float s = 0.f;
        #pragma unroll
        for (int e = 0; e < 64; e++) s += qs[qi * 64 + e] * ks[kj * 64 + e];
        sc[qi][kj] = s * 0.125f;
    }
    __syncthreads();

    if (t < 16) {
        float mx = -1e30f;
        #pragma unroll
        for (int j = 0; j < 16; j++) mx = fmaxf(mx, sc[t][j]);
        float sum = 0.f;
        #pragma unroll
        for (int j = 0; j < 16; j++) { float e = __expf(sc[t][j] - mx); sc[t][j] = e; sum += e; }
        float inv = 1.f / sum;
        #pragma unroll
        for (int j = 0; j < 16; j++) sc[t][j] *= inv;
    }
    __syncthreads();

    {
        int tok = t >> 4;
        int ds  = (t & 15) * 16;
        float a[16];
        #pragma unroll
        for (int kk = 0; kk < 16; kk++) a[kk] = sc[tok][kk];
        float* ob = o + (size_t)w * 16 * 256 + tok * 256 + ds;
        #pragma unroll
        for (int j = 0; j < 16; j++) {
            float s = 0.f;
            #pragma unroll
            for (int kk = 0; kk < 16; kk++) s += a[kk] * vs[kk * 256 + ds + j];
            ob[j] = f2tf32(s);   // next GEMM's A operand
        }
    }
}

// --------------------------- LN(A + B) ---------------------------------------
template <bool SCATTER, bool ROUND>
__global__ void __launch_bounds__(256)
ln_add_kernel(const float* __restrict__ A, const float* __restrict__ Bv,
              const float* __restrict__ gamma, const float* __restrict__ beta,
              float* __restrict__ out) {
    const int warp = threadIdx.x >> 5, lane = threadIdx.x & 31;
    const int row  = blockIdx.x * 8 + warp;
    const float* a = A  + (size_t)row * DMODEL;
    const float* b = Bv + (size_t)row * DMODEL;

    float vals[8];
    float s = 0.f, sq = 0.f;
    #pragma unroll
    for (int j = 0; j < 8; j++) {
        int d = lane + 32 * j;
        float v = a[d] + b[d];
        vals[j] = v; s += v; sq += v * v;
    }
    #pragma unroll
    for (int off = 16; off; off >>= 1) {
        s  += __shfl_xor_sync(0xffffffffu, s,  off);
        sq += __shfl_xor_sync(0xffffffffu, sq, off);
    }
    const float mean = s * (1.f / DMODEL);
    const float var  = sq * (1.f / DMODEL) - mean * mean;
    const float rstd = rsqrtf(var + 1e-5f);

    const int orow = SCATTER ? src_row(row) : row;
    float* op = out + (size_t)orow * DMODEL;
    #pragma unroll
    for (int j = 0; j < 8; j++) {
        int d = lane + 32 * j;
        float v = (vals[j] - mean) * rstd * gamma[d] + beta[d];
        op[d] = ROUND ? f2tf32(v) : v;
    }
}

// ------------------------------ launch --------------------------------------
extern "C" void kernel_launch(void* const* d_in, const int* in_sizes, int n_in,
                              void* d_out, int out_size) {
    const float* x   = (const float*)d_in[0];
    const float* Wq  = (const float*)d_in[1];
    const float* bq  = (const float*)d_in[2];
    const float* Wk  = (const float*)d_in[3];
    const float* bk  = (const float*)d_in[4];
    const float* Wv  = (const float*)d_in[5];
    const float* bv  = (const float*)d_in[6];
    const float* Wo  = (const float*)d_in[7];
    const float* bo  = (const float*)d_in[8];
    const float* g1  = (const float*)d_in[9];
    const float* b1  = (const float*)d_in[10];
    const float* W1  = (const float*)d_in[11];
    const float* bf1 = (const float*)d_in[12];
    const float* W2  = (const float*)d_in[13];
    const float* bf2 = (const float*)d_in[14];
    const float* g2  = (const float*)d_in[15];
    const float* b2  = (const float*)d_in[16];
    float* out = (float*)d_out;

    void *pxg, *pqkv, *po, *pu, *ph, *pf, *pg, *pbtq, *pbto, *pbt1, *pbt2, *pbq;
    cudaGetSymbolAddress(&pxg, g_xg);
    cudaGetSymbolAddress(&pqkv, g_qkv);
    cudaGetSymbolAddress(&po,  g_o);
    cudaGetSymbolAddress(&pu,  g_u);
    cudaGetSymbolAddress(&ph,  g_h);
    cudaGetSymbolAddress(&pf,  g_f);
    cudaGetSymbolAddress(&pg,  g_gg);
    cudaGetSymbolAddress(&pbtq, g_bt_qkv);
    cudaGetSymbolAddress(&pbto, g_bt_o);
    cudaGetSymbolAddress(&pbt1, g_bt_1);
    cudaGetSymbolAddress(&pbt2, g_bt_2);
    cudaGetSymbolAddress(&pbq,  g_bqkv);
    float* xg = (float*)pxg; float* qkv = (float*)pqkv; float* o = (float*)po;
    float* u = (float*)pu; float* h = (float*)ph; float* f = (float*)pf;
    float* gg = (float*)pg;
    float* btq = (float*)pbtq; float* bto = (float*)pbto;
    float* bt1 = (float*)pbt1; float* bt2 = (float*)pbt2;
    float* bqkv = (float*)pbq;

    const int SMEM = 3 * STG;   // 96 KB
    cudaFuncSetAttribute(gemm_mma<false, true >, cudaFuncAttributeMaxDynamicSharedMemorySize, SMEM);
    cudaFuncSetAttribute(gemm_mma<false, false>, cudaFuncAttributeMaxDynamicSharedMemorySize, SMEM);
    cudaFuncSetAttribute(gemm_mma<true,  true >, cudaFuncAttributeMaxDynamicSharedMemorySize, SMEM);

    wtrans<<<(256 * 64   + 255) / 256, 256>>>(Wq, btq, 256, 64,   0,   256);
    wtrans<<<(256 * 64   + 255) / 256, 256>>>(Wk, btq, 256, 64,   64,  256);
    wtrans<<<(256 * 256  + 255) / 256, 256>>>(Wv, btq, 256, 256,  128, 256);
    wtrans<<<(256 * 256  + 255) / 256, 256>>>(Wo, bto, 256, 256,  0,   256);
    wtrans<<<(256 * 1024 + 255) / 256, 256>>>(W1, bt1, 256, 1024, 0,   256);
    wtrans<<<(1024 * 256 + 255) / 256, 256>>>(W2, bt2, 1024, 256, 0,   1024);

    cudaMemcpyAsync(bqkv,       bq, 64  * sizeof(float), cudaMemcpyDeviceToDevice);
    cudaMemcpyAsync(bqkv + 64,  bk, 64  * sizeof(float), cudaMemcpyDeviceToDevice);
    cudaMemcpyAsync(bqkv + 128, bv, 256 * sizeof(float), cudaMemcpyDeviceToDevice);

    const int MB = M_TOK / 128;   // 1024

    gather_kernel<<<NWIN, 256>>>(x, xg);

    // qkv = xg @ [Wq|Wk|Wv]^T + b
    gemm_mma<false, true ><<<dim3(3, MB), 256, SMEM>>>(xg, btq, bqkv, qkv, DQKV, DMODEL);

    attn_kernel<<<NWIN, 256>>>(qkv, o);

    // u = o @ Wo + bo
    gemm_mma<false, false><<<dim3(2, MB), 256, SMEM>>>(o, bto, bo, u, DMODEL, DMODEL);
    // h = LN(xg + u)  (rounded for next GEMM)
    ln_add_kernel<false, true ><<<M_TOK / 8, 256>>>(xg, u, g1, b1, h);

    // f = relu(h @ W1 + bf1) (rounded)
    gemm_mma<true,  true ><<<dim3(8, MB), 256, SMEM>>>(h, bt1, bf1, f, DFF, DMODEL);
    // gg = f @ W2 + bf2
    gemm_mma<false, false><<<dim3(2, MB), 256, SMEM>>>(f, bt2, bf2, gg, DMODEL, DFF);

    // out = scatter(LN(h + gg))
    ln_add_kernel<true, false><<<M_TOK / 8, 256>>>(h, gg, g2, b2, out);
}

// round 4
// speedup vs baseline: 1.9745x; 1.5443x over previous
#include <cuda_runtime.h>
#include <cuda_fp16.h>
#include <cstdint>

// ---------------------------------------------------------------------------
// Round 4: fp16 mma.sync (m16n8k16) GEMMs — same mantissa as tf32, 2x rate,
// half the operand traffic. cp.async 3-stage pipeline + ldmatrix, SW128.
// ---------------------------------------------------------------------------

#define M_TOK  131072
#define DMODEL 256
#define DQKV   384
#define DFF    1024
#define NWIN   8192

// ----------------------------- scratch -------------------------------------
__device__ __half g_xg [(size_t)M_TOK * DMODEL];
__device__ __half g_qkv[(size_t)M_TOK * DQKV];
__device__ __half g_o  [(size_t)M_TOK * DMODEL];
__device__ float  g_u  [(size_t)M_TOK * DMODEL];
__device__ __half g_h  [(size_t)M_TOK * DMODEL];
__device__ __half g_f  [(size_t)M_TOK * DFF];
__device__ float  g_gg [(size_t)M_TOK * DMODEL];
__device__ __half g_bt_qkv[DQKV * DMODEL];   // [N][K]
__device__ __half g_bt_o [DMODEL * DMODEL];
__device__ __half g_bt_1 [DFF * DMODEL];
__device__ __half g_bt_2 [DMODEL * DFF];
__device__ float  g_bqkv[DQKV];

__device__ __forceinline__ int src_row(int m) {
    int t  = m & 15;
    int w  = m >> 4;
    int wj = t & 3, wi = t >> 2;
    int sj = w & 31, si = (w >> 5) & 31, b = w >> 10;
    return ((b * 128) + si * 4 + wi) * 128 + sj * 4 + wj;
}

__device__ __forceinline__ uint32_t smem_u32(const void* p) {
    uint32_t a;
    asm("{ .reg .u64 t; cvta.to.shared.u64 t, %1; cvt.u32.u64 %0, t; }" : "=r"(a) : "l"(p));
    return a;
}
__device__ __forceinline__ void cp16(uint32_t s, const void* g) {
    asm volatile("cp.async.cg.shared.global [%0], [%1], 16;" :: "r"(s), "l"(g));
}
__device__ __forceinline__ void cp_commit() {
    asm volatile("cp.async.commit_group;" ::: "memory");
}
template <int N>
__device__ __forceinline__ void cp_wait() {
    asm volatile("cp.async.wait_group %0;" :: "n"(N) : "memory");
}
__device__ __forceinline__ void ldsm4(uint32_t& r0, uint32_t& r1, uint32_t& r2,
                                      uint32_t& r3, uint32_t addr) {
    asm volatile("ldmatrix.sync.aligned.m8n8.x4.shared.b16 {%0,%1,%2,%3}, [%4];"
                 : "=r"(r0), "=r"(r1), "=r"(r2), "=r"(r3) : "r"(addr));
}
__device__ __forceinline__ void mma_f16(float* c, const uint32_t* a, const uint32_t* b) {
    asm volatile(
        "mma.sync.aligned.m16n8k16.row.col.f32.f16.f16.f32 "
        "{%0,%1,%2,%3}, {%4,%5,%6,%7}, {%8,%9}, {%0,%1,%2,%3};\n"
        : "+f"(c[0]), "+f"(c[1]), "+f"(c[2]), "+f"(c[3])
        : "r"(a[0]), "r"(a[1]), "r"(a[2]), "r"(a[3]), "r"(b[0]), "r"(b[1]));
}
__device__ __forceinline__ uint32_t swz(uint32_t b) { return b ^ ((b >> 3) & 0x70); }

// ------------------------ fused weight transpose -----------------------------
__global__ void wtrans_all(const float* __restrict__ Wq, const float* __restrict__ Wk,
                           const float* __restrict__ Wv, const float* __restrict__ Wo,
                           const float* __restrict__ W1, const float* __restrict__ W2,
                           __half* btq, __half* bto, __half* bt1, __half* bt2) {
    int li = blockIdx.x * 256 + threadIdx.x;
    const float* W; __half* dst; int N, nofs, ldk;
    if (li < 16384)                 { W = Wq; dst = btq; N = 64;   nofs = 0;   ldk = 256;  }
    else if ((li -= 16384) < 16384) { W = Wk; dst = btq; N = 64;   nofs = 64;  ldk = 256;  }
    else if ((li -= 16384) < 65536) { W = Wv; dst = btq; N = 256;  nofs = 128; ldk = 256;  }
    else if ((li -= 65536) < 65536) { W = Wo; dst = bto; N = 256;  nofs = 0;   ldk = 256;  }
    else if ((li -= 65536) < 262144){ W = W1; dst = bt1; N = 1024; nofs = 0;   ldk = 256;  }
    else if ((li -= 262144) < 262144){W = W2; dst = bt2; N = 256;  nofs = 0;   ldk = 1024; }
    else return;
    int k = li / N, n = li % N;
    dst[(size_t)(nofs + n) * ldk + k] = __float2half_rn(W[li]);
}

// ----------------------------- gather + round --------------------------------
__global__ void gather_kernel(const float* __restrict__ x, __half* __restrict__ xg) {
    const float4* x4 = reinterpret_cast<const float4*>(x);
    int base = blockIdx.x * 1024 + threadIdx.x;
    #pragma unroll
    for (int i = 0; i < 4; i++) {
        int idx = base + i * 256;
        int m = idx >> 6, c = idx & 63;
        float4 v = x4[src_row(m) * 64 + c];
        __half2 h0 = __floats2half2_rn(v.x, v.y);
        __half2 h1 = __floats2half2_rn(v.z, v.w);
        uint2 u;
        u.x = *reinterpret_cast<uint32_t*>(&h0);
        u.y = *reinterpret_cast<uint32_t*>(&h1);
        *reinterpret_cast<uint2*>(xg + (size_t)idx * 4) = u;
    }
}

// ------------------------------- GEMM ----------------------------------------
// C[M,N] = A[M,K] @ Bt^T + bias (+relu). A,Bt half. BM=BN=128, BK=64, 3 stages.
#define ABYTES 16384
#define STG    32768
template <bool RELU, typename TOUT>
__global__ void __launch_bounds__(256, 2)
gemm_mma(const __half* __restrict__ A, const __half* __restrict__ Bt,
         const float* __restrict__ bias, TOUT* __restrict__ C,
         int N, int K)
{
    extern __shared__ char smem[];
    const uint32_t sb = smem_u32(smem);

    const int tid  = threadIdx.x;
    const int lane = tid & 31, warp = tid >> 5;
    const int wm = warp >> 2, wn = warp & 3;
    const int lq = lane >> 2, lr = lane & 3;
    const int row0 = blockIdx.y * 128;
    const int n0   = blockIdx.x * 128;
    const int KT   = K >> 6;

    float acc[4][4][4];
    #pragma unroll
    for (int mi = 0; mi < 4; mi++)
        #pragma unroll
        for (int ni = 0; ni < 4; ni++)
            #pragma unroll
            for (int j = 0; j < 4; j++) acc[mi][ni][j] = 0.f;

    // cp.async: 128 rows x 8 segs(16B) per tile; 256 thr x 4 iters each of A,B
    const int r_ld = tid >> 3;
    const int cseg = tid & 7;
    const size_t aRow0 = (size_t)(row0 + r_ld) * K;
    const size_t bRow0 = (size_t)(n0   + r_ld) * K;
    const uint32_t sOff = swz(r_ld * 128 + cseg * 16);

    auto load_stage = [&](int kt, int buf) {
        const int kofs = kt * 64 + cseg * 8;     // halves
        const uint32_t aBase = sb + buf * STG;
        const uint32_t bBase = aBase + ABYTES;
        #pragma unroll
        for (int i = 0; i < 4; i++) {
            cp16(aBase + sOff + i * 4096, A  + aRow0 + (size_t)i * 32 * K + kofs);
            cp16(bBase + sOff + i * 4096, Bt + bRow0 + (size_t)i * 32 * K + kofs);
        }
        cp_commit();
    };

    const int quad = lane >> 3, r8 = lane & 7;
    const int aRowL  = wm * 64 + (quad & 1) * 8 + r8;   // + mi*16
    const int aKoffB = (quad >> 1) * 16;                // bytes, + ks*32
    const int bRowL  = wn * 32 + (quad >> 1) * 8 + r8;  // + nt*16
    const int bKoffB = (quad & 1) * 16;                 // bytes, + ks*32

    auto compute = [&](int buf) {
        const uint32_t aBase = sb + buf * STG;
        const uint32_t bBase = aBase + ABYTES;
        #pragma unroll
        for (int ks = 0; ks < 4; ks++) {
            uint32_t af[4][4], bf[2][4];
            #pragma unroll
            for (int mi = 0; mi < 4; mi++) {
                int row = aRowL + mi * 16;
                ldsm4(af[mi][0], af[mi][1], af[mi][2], af[mi][3],
                      aBase + swz(row * 128 + ks * 32 + aKoffB));
            }
            #pragma unroll
            for (int nt = 0; nt < 2; nt++) {
                int row = bRowL + nt * 16;
                ldsm4(bf[nt][0], bf[nt][1], bf[nt][2], bf[nt][3],
                      bBase + swz(row * 128 + ks * 32 + bKoffB));
            }
            #pragma unroll
            for (int mi = 0; mi < 4; mi++) {
                #pragma unroll
                for (int nt = 0; nt < 2; nt++) {
                    mma_f16(acc[mi][nt * 2 + 0], af[mi], &bf[nt][0]);
                    mma_f16(acc[mi][nt * 2 + 1], af[mi], &bf[nt][2]);
                }
            }
        }
    };

    load_stage(0, 0);
    load_stage(1, 1);
    for (int kt = 0; kt < KT; kt++) {
        cp_wait<1>();
        __syncthreads();
        if (kt + 2 < KT) load_stage(kt + 2, (kt + 2) % 3);
        else cp_commit();
        compute(kt % 3);
    }

    // epilogue
    #pragma unroll
    for (int mi = 0; mi < 4; mi++) {
        #pragma unroll
        for (int ni = 0; ni < 4; ni++) {
            const int r0 = row0 + wm * 64 + mi * 16 + lq;
            const int c0 = n0 + wn * 32 + ni * 8 + 2 * lr;
            const float b0 = __ldg(bias + c0), b1 = __ldg(bias + c0 + 1);
            float v0 = acc[mi][ni][0] + b0;
            float v1 = acc[mi][ni][1] + b1;
            float v2 = acc[mi][ni][2] + b0;
            float v3 = acc[mi][ni][3] + b1;
            if (RELU) {
                v0 = fmaxf(v0, 0.f); v1 = fmaxf(v1, 0.f);
                v2 = fmaxf(v2, 0.f); v3 = fmaxf(v3, 0.f);
            }
            if (sizeof(TOUT) == 2) {
                __half2* p0 = reinterpret_cast<__half2*>((__half*)C + (size_t)r0 * N + c0);
                __half2* p1 = reinterpret_cast<__half2*>((__half*)C + (size_t)(r0 + 8) * N + c0);
                *p0 = __floats2half2_rn(v0, v1);
                *p1 = __floats2half2_rn(v2, v3);
            } else {
                *reinterpret_cast<float2*>((float*)C + (size_t)r0 * N + c0)       = make_float2(v0, v1);
                *reinterpret_cast<float2*>((float*)C + (size_t)(r0 + 8) * N + c0) = make_float2(v2, v3);
            }
        }
    }
}

// --------------------------- attention (per window) -------------------------
__global__ void __launch_bounds__(256)
attn_kernel(const __half* __restrict__ qkv, __half* __restrict__ o) {
    __shared__ float qs[16 * 64];
    __shared__ float ks[16 * 64];
    __shared__ float vs[16 * 256];
    __shared__ float sc[16][17];

    const int w = blockIdx.x, t = threadIdx.x;
    const __half* base = qkv + (size_t)w * 16 * DQKV;

    {   // q,k: 128 half8-vectors each
        int which = t >> 7;            // 0 -> q, 1 -> k
        int vi = t & 127;
        int r = vi >> 3, c8 = (vi & 7) * 8;
        uint4 raw = *reinterpret_cast<const uint4*>(base + r * DQKV + which * 64 + c8);
        const __half2* hp = reinterpret_cast<const __half2*>(&raw);
        float* dst = (which ? ks : qs) + r * 64 + c8;
        #pragma unroll
        for (int p = 0; p < 4; p++) {
            float2 f = __half22float2(hp[p]);
            dst[p * 2] = f.x; dst[p * 2 + 1] = f.y;
        }
    }
    #pragma unroll
    for (int it = 0; it < 2; it++) {    // v: 512 half8-vectors
        int vi = t + it * 256;
        int r = vi >> 5, c8 = (vi & 31) * 8;
        uint4 raw = *reinterpret_cast<const uint4*>(base + r * DQKV + 128 + c8);
        const __half2* hp = reinterpret_cast<const __half2*>(&raw);
        float* dst = vs + r * 256 + c8;
        #pragma unroll
        for (int p = 0; p < 4; p++) {
            float2 f = __half22float2(hp[p]);
            dst[p * 2] = f.x; dst[p * 2 + 1] = f.y;
        }
    }
    __syncthreads();

    {
        int qi = t >> 4, kj = t & 15;
        float s = 0.f;
        #pragma unroll
        for (int e = 0; e < 64; e++) s += qs[qi * 64 + e] * ks[kj * 64 + e];
        sc[qi][kj] = s * 0.125f;
    }
    __syncthreads();

    if (t < 16) {
        float mx = -1e30f;
        #pragma unroll
        for (int j = 0; j < 16; j++) mx = fmaxf(mx, sc[t][j]);
        float sum = 0.f;
        #pragma unroll
        for (int j = 0; j < 16; j++) { float e = __expf(sc[t][j] - mx); sc[t][j] = e; sum += e; }
        float inv = 1.f / sum;
        #pragma unroll
        for (int j = 0; j < 16; j++) sc[t][j] *= inv;
    }
    __syncthreads();

    {
        int tok = t >> 4;
        int ds  = (t & 15) * 16;
        float a[16];
        #pragma unroll
        for (int kk = 0; kk < 16; kk++) a[kk] = sc[tok][kk];
        __half hv[16];
        #pragma unroll
        for (int j = 0; j < 16; j++) {
            float s = 0.f;
            #pragma unroll
            for (int kk = 0; kk < 16; kk++) s += a[kk] * vs[kk * 256 + ds + j];
            hv[j] = __float2half_rn(s);
        }
        *reinterpret_cast<uint4*>(o + (size_t)w * 16 * 256 + tok * 256 + ds) =
            *reinterpret_cast<uint4*>(hv);
        *reinterpret_cast<uint4*>(o + (size_t)w * 16 * 256 + tok * 256 + ds + 8) =
            *reinterpret_cast<uint4*>(hv + 8);
    }
}

// --------------------------- LN(A + B) ---------------------------------------
template <bool SCATTER, typename TOUT>
__global__ void __launch_bounds__(256)
ln_add_kernel(const __half* __restrict__ A, const float* __restrict__ Bv,
              const float* __restrict__ gamma, const float* __restrict__ beta,
              TOUT* __restrict__ out) {
    const int warp = threadIdx.x >> 5, lane = threadIdx.x & 31;
    const int row  = blockIdx.x * 8 + warp;
    const int d0   = lane * 8;
    const __half* a = A  + (size_t)row * DMODEL + d0;
    const float*  b = Bv + (size_t)row * DMODEL + d0;

    uint4 ar = *reinterpret_cast<const uint4*>(a);
    const __half2* ah = reinterpret_cast<const __half2*>(&ar);
    float4 b0 = *reinterpret_cast<const float4*>(b);
    float4 b1 = *reinterpret_cast<const float4*>(b + 4);

    float vals[8];
    {
        float2 f0 = __half22float2(ah[0]); vals[0] = f0.x + b0.x; vals[1] = f0.y + b0.y;
        float2 f1 = __half22float2(ah[1]); vals[2] = f1.x + b0.z; vals[3] = f1.y + b0.w;
        float2 f2 = __half22float2(ah[2]); vals[4] = f2.x + b1.x; vals[5] = f2.y + b1.y;
        float2 f3 = __half22float2(ah[3]); vals[6] = f3.x + b1.z; vals[7] = f3.y + b1.w;
    }
    float s = 0.f, sq = 0.f;
    #pragma unroll
    for (int j = 0; j < 8; j++) { s += vals[j]; sq += vals[j] * vals[j]; }
    #pragma unroll
    for (int off = 16; off; off >>= 1) {
        s  += __shfl_xor_sync(0xffffffffu, s,  off);
        sq += __shfl_xor_sync(0xffffffffu, sq, off);
    }
    const float mean = s * (1.f / DMODEL);
    const float var  = sq * (1.f / DMODEL) - mean * mean;
    const float rstd = rsqrtf(var + 1e-5f);

    float4 gm0 = *reinterpret_cast<const float4*>(gamma + d0);
    float4 gm1 = *reinterpret_cast<const float4*>(gamma + d0 + 4);
    float4 bt0 = *reinterpret_cast<const float4*>(beta + d0);
    float4 bt1 = *reinterpret_cast<const float4*>(beta + d0 + 4);
    float g[8] = {gm0.x, gm0.y, gm0.z, gm0.w, gm1.x, gm1.y, gm1.z, gm1.w};
    float bb[8] = {bt0.x, bt0.y, bt0.z, bt0.w, bt1.x, bt1.y, bt1.z, bt1.w};

    float r[8];
    #pragma unroll
    for (int j = 0; j < 8; j++) r[j] = (vals[j] - mean) * rstd * g[j] + bb[j];

    const int orow = SCATTER ? src_row(row) : row;
    if (sizeof(TOUT) == 2) {
        __half hv[8];
        #pragma unroll
        for (int j = 0; j < 8; j++) hv[j] = __float2half_rn(r[j]);
        *reinterpret_cast<uint4*>((__half*)out + (size_t)orow * DMODEL + d0) =
            *reinterpret_cast<uint4*>(hv);
    } else {
        float* op = (float*)out + (size_t)orow * DMODEL + d0;
        *reinterpret_cast<float4*>(op)     = make_float4(r[0], r[1], r[2], r[3]);
        *reinterpret_cast<float4*>(op + 4) = make_float4(r[4], r[5], r[6], r[7]);
    }
}

// ------------------------------ launch --------------------------------------
extern "C" void kernel_launch(void* const* d_in, const int* in_sizes, int n_in,
                              void* d_out, int out_size) {
    const float* x   = (const float*)d_in[0];
    const float* Wq  = (const float*)d_in[1];
    const float* bq  = (const float*)d_in[2];
    const float* Wk  = (const float*)d_in[3];
    const float* bk  = (const float*)d_in[4];
    const float* Wv  = (const float*)d_in[5];
    const float* bv  = (const float*)d_in[6];
    const float* Wo  = (const float*)d_in[7];
    const float* bo  = (const float*)d_in[8];
    const float* g1  = (const float*)d_in[9];
    const float* b1  = (const float*)d_in[10];
    const float* W1  = (const float*)d_in[11];
    const float* bf1 = (const float*)d_in[12];
    const float* W2  = (const float*)d_in[13];
    const float* bf2 = (const float*)d_in[14];
    const float* g2  = (const float*)d_in[15];
    const float* b2  = (const float*)d_in[16];
    float* out = (float*)d_out;

    void *pxg, *pqkv, *po, *pu, *ph, *pf, *pg, *pbtq, *pbto, *pbt1, *pbt2, *pbq;
    cudaGetSymbolAddress(&pxg, g_xg);
    cudaGetSymbolAddress(&pqkv, g_qkv);
    cudaGetSymbolAddress(&po,  g_o);
    cudaGetSymbolAddress(&pu,  g_u);
    cudaGetSymbolAddress(&ph,  g_h);
    cudaGetSymbolAddress(&pf,  g_f);
    cudaGetSymbolAddress(&pg,  g_gg);
    cudaGetSymbolAddress(&pbtq, g_bt_qkv);
    cudaGetSymbolAddress(&pbto, g_bt_o);
    cudaGetSymbolAddress(&pbt1, g_bt_1);
    cudaGetSymbolAddress(&pbt2, g_bt_2);
    cudaGetSymbolAddress(&pbq,  g_bqkv);
    __half* xg = (__half*)pxg; __half* qkv = (__half*)pqkv; __half* o = (__half*)po;
    float* u = (float*)pu; __half* h = (__half*)ph; __half* f = (__half*)pf;
    float* gg = (float*)pg;
    __half* btq = (__half*)pbtq; __half* bto = (__half*)pbto;
    __half* bt1 = (__half*)pbt1; __half* bt2 = (__half*)pbt2;
    float* bqkv = (float*)pbq;

    const int SMEM = 3 * STG;   // 96 KB
    cudaFuncSetAttribute(gemm_mma<false, __half>, cudaFuncAttributeMaxDynamicSharedMemorySize, SMEM);
    cudaFuncSetAttribute(gemm_mma<false, float >, cudaFuncAttributeMaxDynamicSharedMemorySize, SMEM);
    cudaFuncSetAttribute(gemm_mma<true,  __half>, cudaFuncAttributeMaxDynamicSharedMemorySize, SMEM);

    wtrans_all<<<2688, 256>>>(Wq, Wk, Wv, Wo, W1, W2, btq, bto, bt1, bt2);

    cudaMemcpyAsync(bqkv,       bq, 64  * sizeof(float), cudaMemcpyDeviceToDevice);
    cudaMemcpyAsync(bqkv + 64,  bk, 64  * sizeof(float), cudaMemcpyDeviceToDevice);
    cudaMemcpyAsync(bqkv + 128, bv, 256 * sizeof(float), cudaMemcpyDeviceToDevice);

    const int MB = M_TOK / 128;   // 1024

    gather_kernel<<<NWIN, 256>>>(x, xg);

    // qkv = xg @ [Wq|Wk|Wv]^T + b
    gemm_mma<false, __half><<<dim3(3, MB), 256, SMEM>>>(xg, btq, bqkv, qkv, DQKV, DMODEL);

    attn_kernel<<<NWIN, 256>>>(qkv, o);

    // u = o @ Wo + bo
    gemm_mma<false, float ><<<dim3(2, MB), 256, SMEM>>>(o, bto, bo, u, DMODEL, DMODEL);
    // h = LN(xg + u) -> half
    ln_add_kernel<false, __half><<<M_TOK / 8, 256>>>(xg, u, g1, b1, h);

    // f = relu(h @ W1 + bf1) -> half
    gemm_mma<true,  __half><<<dim3(8, MB), 256, SMEM>>>(h, bt1, bf1, f, DFF, DMODEL);
    // gg = f @ W2 + bf2 -> fp32
    gemm_mma<false, float ><<<dim3(2, MB), 256, SMEM>>>(f, bt2, bf2, gg, DMODEL, DFF);

    // out = scatter(LN(h + gg))
    ln_add_kernel<true, float><<<M_TOK / 8, 256>>>(h, gg, g2, b2, out);
}

// round 5
// speedup vs baseline: 2.5923x; 1.3129x over previous
#include <cuda_runtime.h>
#include <cuda_fp16.h>
#include <cstdint>

// ---------------------------------------------------------------------------
// Round 5: fix attn_kernel smem bank conflicts (K transposed + AV col remap),
// u/gg stored half. GEMMs unchanged (fp16 mma.sync, cp.async 3-stage).
// ---------------------------------------------------------------------------

#define M_TOK  131072
#define DMODEL 256
#define DQKV   384
#define DFF    1024
#define NWIN   8192

// ----------------------------- scratch -------------------------------------
__device__ __half g_xg [(size_t)M_TOK * DMODEL];
__device__ __half g_qkv[(size_t)M_TOK * DQKV];
__device__ __half g_o  [(size_t)M_TOK * DMODEL];
__device__ __half g_u  [(size_t)M_TOK * DMODEL];
__device__ __half g_h  [(size_t)M_TOK * DMODEL];
__device__ __half g_f  [(size_t)M_TOK * DFF];
__device__ __half g_gg [(size_t)M_TOK * DMODEL];
__device__ __half g_bt_qkv[DQKV * DMODEL];   // [N][K]
__device__ __half g_bt_o [DMODEL * DMODEL];
__device__ __half g_bt_1 [DFF * DMODEL];
__device__ __half g_bt_2 [DMODEL * DFF];
__device__ float  g_bqkv[DQKV];

__device__ __forceinline__ int src_row(int m) {
    int t  = m & 15;
    int w  = m >> 4;
    int wj = t & 3, wi = t >> 2;
    int sj = w & 31, si = (w >> 5) & 31, b = w >> 10;
    return ((b * 128) + si * 4 + wi) * 128 + sj * 4 + wj;
}

__device__ __forceinline__ uint32_t smem_u32(const void* p) {
    uint32_t a;
    asm("{ .reg .u64 t; cvta.to.shared.u64 t, %1; cvt.u32.u64 %0, t; }" : "=r"(a) : "l"(p));
    return a;
}
__device__ __forceinline__ void cp16(uint32_t s, const void* g) {
    asm volatile("cp.async.cg.shared.global [%0], [%1], 16;" :: "r"(s), "l"(g));
}
__device__ __forceinline__ void cp_commit() {
    asm volatile("cp.async.commit_group;" ::: "memory");
}
template <int N>
__device__ __forceinline__ void cp_wait() {
    asm volatile("cp.async.wait_group %0;" :: "n"(N) : "memory");
}
__device__ __forceinline__ void ldsm4(uint32_t& r0, uint32_t& r1, uint32_t& r2,
                                      uint32_t& r3, uint32_t addr) {
    asm volatile("ldmatrix.sync.aligned.m8n8.x4.shared.b16 {%0,%1,%2,%3}, [%4];"
                 : "=r"(r0), "=r"(r1), "=r"(r2), "=r"(r3) : "r"(addr));
}
__device__ __forceinline__ void mma_f16(float* c, const uint32_t* a, const uint32_t* b) {
    asm volatile(
        "mma.sync.aligned.m16n8k16.row.col.f32.f16.f16.f32 "
        "{%0,%1,%2,%3}, {%4,%5,%6,%7}, {%8,%9}, {%0,%1,%2,%3};\n"
        : "+f"(c[0]), "+f"(c[1]), "+f"(c[2]), "+f"(c[3])
        : "r"(a[0]), "r"(a[1]), "r"(a[2]), "r"(a[3]), "r"(b[0]), "r"(b[1]));
}
__device__ __forceinline__ uint32_t swz(uint32_t b) { return b ^ ((b >> 3) & 0x70); }

// ------------------------ fused weight transpose -----------------------------
__global__ void wtrans_all(const float* __restrict__ Wq, const float* __restrict__ Wk,
                           const float* __restrict__ Wv, const float* __restrict__ Wo,
                           const float* __restrict__ W1, const float* __restrict__ W2,
                           __half* btq, __half* bto, __half* bt1, __half* bt2) {
    int li = blockIdx.x * 256 + threadIdx.x;
    const float* W; __half* dst; int N, nofs, ldk;
    if (li < 16384)                 { W = Wq; dst = btq; N = 64;   nofs = 0;   ldk = 256;  }
    else if ((li -= 16384) < 16384) { W = Wk; dst = btq; N = 64;   nofs = 64;  ldk = 256;  }
    else if ((li -= 16384) < 65536) { W = Wv; dst = btq; N = 256;  nofs = 128; ldk = 256;  }
    else if ((li -= 65536) < 65536) { W = Wo; dst = bto; N = 256;  nofs = 0;   ldk = 256;  }
    else if ((li -= 65536) < 262144){ W = W1; dst = bt1; N = 1024; nofs = 0;   ldk = 256;  }
    else if ((li -= 262144) < 262144){W = W2; dst = bt2; N = 256;  nofs = 0;   ldk = 1024; }
    else return;
    int k = li / N, n = li % N;
    dst[(size_t)(nofs + n) * ldk + k] = __float2half_rn(W[li]);
}

// ----------------------------- gather + round --------------------------------
__global__ void gather_kernel(const float* __restrict__ x, __half* __restrict__ xg) {
    const float4* x4 = reinterpret_cast<const float4*>(x);
    int base = blockIdx.x * 1024 + threadIdx.x;
    #pragma unroll
    for (int i = 0; i < 4; i++) {
        int idx = base + i * 256;
        int m = idx >> 6, c = idx & 63;
        float4 v = x4[src_row(m) * 64 + c];
        __half2 h0 = __floats2half2_rn(v.x, v.y);
        __half2 h1 = __floats2half2_rn(v.z, v.w);
        uint2 u;
        u.x = *reinterpret_cast<uint32_t*>(&h0);
        u.y = *reinterpret_cast<uint32_t*>(&h1);
        *reinterpret_cast<uint2*>(xg + (size_t)idx * 4) = u;
    }
}

// ------------------------------- GEMM ----------------------------------------
#define ABYTES 16384
#define STG    32768
template <bool RELU, typename TOUT>
__global__ void __launch_bounds__(256, 2)
gemm_mma(const __half* __restrict__ A, const __half* __restrict__ Bt,
         const float* __restrict__ bias, TOUT* __restrict__ C,
         int N, int K)
{
    extern __shared__ char smem[];
    const uint32_t sb = smem_u32(smem);

    const int tid  = threadIdx.x;
    const int lane = tid & 31, warp = tid >> 5;
    const int wm = warp >> 2, wn = warp & 3;
    const int lq = lane >> 2, lr = lane & 3;
    const int row0 = blockIdx.y * 128;
    const int n0   = blockIdx.x * 128;
    const int KT   = K >> 6;

    float acc[4][4][4];
    #pragma unroll
    for (int mi = 0; mi < 4; mi++)
        #pragma unroll
        for (int ni = 0; ni < 4; ni++)
            #pragma unroll
            for (int j = 0; j < 4; j++) acc[mi][ni][j] = 0.f;

    const int r_ld = tid >> 3;
    const int cseg = tid & 7;
    const size_t aRow0 = (size_t)(row0 + r_ld) * K;
    const size_t bRow0 = (size_t)(n0   + r_ld) * K;
    const uint32_t sOff = swz(r_ld * 128 + cseg * 16);

    auto load_stage = [&](int kt, int buf) {
        const int kofs = kt * 64 + cseg * 8;
        const uint32_t aBase = sb + buf * STG;
        const uint32_t bBase = aBase + ABYTES;
        #pragma unroll
        for (int i = 0; i < 4; i++) {
            cp16(aBase + sOff + i * 4096, A  + aRow0 + (size_t)i * 32 * K + kofs);
            cp16(bBase + sOff + i * 4096, Bt + bRow0 + (size_t)i * 32 * K + kofs);
        }
        cp_commit();
    };

    const int quad = lane >> 3, r8 = lane & 7;
    const int aRowL  = wm * 64 + (quad & 1) * 8 + r8;
    const int aKoffB = (quad >> 1) * 16;
    const int bRowL  = wn * 32 + (quad >> 1) * 8 + r8;
    const int bKoffB = (quad & 1) * 16;

    auto compute = [&](int buf) {
        const uint32_t aBase = sb + buf * STG;
        const uint32_t bBase = aBase + ABYTES;
        #pragma unroll
        for (int ks = 0; ks < 4; ks++) {
            uint32_t af[4][4], bf[2][4];
            #pragma unroll
            for (int mi = 0; mi < 4; mi++) {
                int row = aRowL + mi * 16;
                ldsm4(af[mi][0], af[mi][1], af[mi][2], af[mi][3],
                      aBase + swz(row * 128 + ks * 32 + aKoffB));
            }
            #pragma unroll
            for (int nt = 0; nt < 2; nt++) {
                int row = bRowL + nt * 16;
                ldsm4(bf[nt][0], bf[nt][1], bf[nt][2], bf[nt][3],
                      bBase + swz(row * 128 + ks * 32 + bKoffB));
            }
            #pragma unroll
            for (int mi = 0; mi < 4; mi++) {
                #pragma unroll
                for (int nt = 0; nt < 2; nt++) {
                    mma_f16(acc[mi][nt * 2 + 0], af[mi], &bf[nt][0]);
                    mma_f16(acc[mi][nt * 2 + 1], af[mi], &bf[nt][2]);
                }
            }
        }
    };

    load_stage(0, 0);
    load_stage(1, 1);
    for (int kt = 0; kt < KT; kt++) {
        cp_wait<1>();
        __syncthreads();
        if (kt + 2 < KT) load_stage(kt + 2, (kt + 2) % 3);
        else cp_commit();
        compute(kt % 3);
    }

    #pragma unroll
    for (int mi = 0; mi < 4; mi++) {
        #pragma unroll
        for (int ni = 0; ni < 4; ni++) {
            const int r0 = row0 + wm * 64 + mi * 16 + lq;
            const int c0 = n0 + wn * 32 + ni * 8 + 2 * lr;
            const float b0 = __ldg(bias + c0), b1 = __ldg(bias + c0 + 1);
            float v0 = acc[mi][ni][0] + b0;
            float v1 = acc[mi][ni][1] + b1;
            float v2 = acc[mi][ni][2] + b0;
            float v3 = acc[mi][ni][3] + b1;
            if (RELU) {
                v0 = fmaxf(v0, 0.f); v1 = fmaxf(v1, 0.f);
                v2 = fmaxf(v2, 0.f); v3 = fmaxf(v3, 0.f);
            }
            if (sizeof(TOUT) == 2) {
                __half2* p0 = reinterpret_cast<__half2*>((__half*)C + (size_t)r0 * N + c0);
                __half2* p1 = reinterpret_cast<__half2*>((__half*)C + (size_t)(r0 + 8) * N + c0);
                *p0 = __floats2half2_rn(v0, v1);
                *p1 = __floats2half2_rn(v2, v3);
            } else {
                *reinterpret_cast<float2*>((float*)C + (size_t)r0 * N + c0)       = make_float2(v0, v1);
                *reinterpret_cast<float2*>((float*)C + (size_t)(r0 + 8) * N + c0) = make_float2(v2, v3);
            }
        }
    }
}

// --------------------------- attention (per window) -------------------------
// Conflict-free smem layout: K transposed (stride 17), AV phase col-major map.
__global__ void __launch_bounds__(256)
attn_kernel(const __half* __restrict__ qkv, __half* __restrict__ o) {
    __shared__ float qs[16 * 64];
    __shared__ float ksT[64 * 17];         // ksT[e*17 + kj]
    __shared__ float vs[16 * 256];
    __shared__ float sc[16][17];

    const int w = blockIdx.x, t = threadIdx.x;
    const __half* base = qkv + (size_t)w * 16 * DQKV;

    {   // q,k: 128 half8-vectors each; k goes in transposed
        int which = t >> 7;
        int vi = t & 127;
        int r = vi >> 3, c8 = (vi & 7) * 8;
        uint4 raw = *reinterpret_cast<const uint4*>(base + r * DQKV + which * 64 + c8);
        const __half2* hp = reinterpret_cast<const __half2*>(&raw);
        if (which == 0) {
            float* dst = qs + r * 64 + c8;
            #pragma unroll
            for (int p = 0; p < 4; p++) {
                float2 f = __half22float2(hp[p]);
                dst[p * 2] = f.x; dst[p * 2 + 1] = f.y;
            }
        } else {
            #pragma unroll
            for (int p = 0; p < 4; p++) {
                float2 f = __half22float2(hp[p]);
                ksT[(c8 + 2 * p)     * 17 + r] = f.x;
                ksT[(c8 + 2 * p + 1) * 17 + r] = f.y;
            }
        }
    }
    #pragma unroll
    for (int it = 0; it < 2; it++) {
        int vi = t + it * 256;
        int r = vi >> 5, c8 = (vi & 31) * 8;
        uint4 raw = *reinterpret_cast<const uint4*>(base + r * DQKV + 128 + c8);
        const __half2* hp = reinterpret_cast<const __half2*>(&raw);
        float* dst = vs + r * 256 + c8;
        #pragma unroll
        for (int p = 0; p < 4; p++) {
            float2 f = __half22float2(hp[p]);
            dst[p * 2] = f.x; dst[p * 2 + 1] = f.y;
        }
    }
    __syncthreads();

    {   // scores: thread (qi,kj); ksT read = 16 consecutive banks, qs = broadcast
        int qi = t >> 4, kj = t & 15;
        float s = 0.f;
        #pragma unroll
        for (int e = 0; e < 64; e++) s += qs[qi * 64 + e] * ksT[e * 17 + kj];
        sc[qi][kj] = s * 0.125f;
    }
    __syncthreads();

    if (t < 16) {
        float mx = -1e30f;
        #pragma unroll
        for (int j = 0; j < 16; j++) mx = fmaxf(mx, sc[t][j]);
        float sum = 0.f;
        #pragma unroll
        for (int j = 0; j < 16; j++) { float e = __expf(sc[t][j] - mx); sc[t][j] = e; sum += e; }
        float inv = 1.f / sum;
        #pragma unroll
        for (int j = 0; j < 16; j++) sc[t][j] *= inv;
    }
    __syncthreads();

    {   // o = attn @ v : thread owns cols c0+16j (conflict-free vs reads)
        int tok = t >> 4;
        int c0  = t & 15;
        float a[16];
        #pragma unroll
        for (int kk = 0; kk < 16; kk++) a[kk] = sc[tok][kk];
        __half* ob = o + (size_t)w * 16 * 256 + tok * 256;
        #pragma unroll
        for (int j = 0; j < 16; j++) {
            int col = c0 + 16 * j;
            float s = 0.f;
            #pragma unroll
            for (int kk = 0; kk < 16; kk++) s += a[kk] * vs[kk * 256 + col];
            ob[col] = __float2half_rn(s);
        }
    }
}

// --------------------------- LN(A + B) ---------------------------------------
template <bool SCATTER, typename TOUT>
__global__ void __launch_bounds__(256)
ln_add_kernel(const __half* __restrict__ A, const __half* __restrict__ Bv,
              const float* __restrict__ gamma, const float* __restrict__ beta,
              TOUT* __restrict__ out) {
    const int warp = threadIdx.x >> 5, lane = threadIdx.x & 31;
    const int row  = blockIdx.x * 8 + warp;
    const int d0   = lane * 8;
    const __half* a = A  + (size_t)row * DMODEL + d0;
    const __half* b = Bv + (size_t)row * DMODEL + d0;

    uint4 ar = *reinterpret_cast<const uint4*>(a);
    uint4 br = *reinterpret_cast<const uint4*>(b);
    const __half2* ah = reinterpret_cast<const __half2*>(&ar);
    const __half2* bh = reinterpret_cast<const __half2*>(&br);

    float vals[8];
    #pragma unroll
    for (int p = 0; p < 4; p++) {
        float2 fa = __half22float2(ah[p]);
        float2 fb = __half22float2(bh[p]);
        vals[p * 2]     = fa.x + fb.x;
        vals[p * 2 + 1] = fa.y + fb.y;
    }
    float s = 0.f, sq = 0.f;
    #pragma unroll
    for (int j = 0; j < 8; j++) { s += vals[j]; sq += vals[j] * vals[j]; }
    #pragma unroll
    for (int off = 16; off; off >>= 1) {
        s  += __shfl_xor_sync(0xffffffffu, s,  off);
        sq += __shfl_xor_sync(0xffffffffu, sq, off);
    }
    const float mean = s * (1.f / DMODEL);
    const float var  = sq * (1.f / DMODEL) - mean * mean;
    const float rstd = rsqrtf(var + 1e-5f);

    float4 gm0 = *reinterpret_cast<const float4*>(gamma + d0);
    float4 gm1 = *reinterpret_cast<const float4*>(gamma + d0 + 4);
    float4 bt0 = *reinterpret_cast<const float4*>(beta + d0);
    float4 bt1 = *reinterpret_cast<const float4*>(beta + d0 + 4);
    float g[8] = {gm0.x, gm0.y, gm0.z, gm0.w, gm1.x, gm1.y, gm1.z, gm1.w};
    float bb[8] = {bt0.x, bt0.y, bt0.z, bt0.w, bt1.x, bt1.y, bt1.z, bt1.w};

    float r[8];
    #pragma unroll
    for (int j = 0; j < 8; j++) r[j] = (vals[j] - mean) * rstd * g[j] + bb[j];

    const int orow = SCATTER ? src_row(row) : row;
    if (sizeof(TOUT) == 2) {
        __half hv[8];
        #pragma unroll
        for (int j = 0; j < 8; j++) hv[j] = __float2half_rn(r[j]);
        *reinterpret_cast<uint4*>((__half*)out + (size_t)orow * DMODEL + d0) =
            *reinterpret_cast<uint4*>(hv);
    } else {
        float* op = (float*)out + (size_t)orow * DMODEL + d0;
        *reinterpret_cast<float4*>(op)     = make_float4(r[0], r[1], r[2], r[3]);
        *reinterpret_cast<float4*>(op + 4) = make_float4(r[4], r[5], r[6], r[7]);
    }
}

// ------------------------------ launch --------------------------------------
extern "C" void kernel_launch(void* const* d_in, const int* in_sizes, int n_in,
                              void* d_out, int out_size) {
    const float* x   = (const float*)d_in[0];
    const float* Wq  = (const float*)d_in[1];
    const float* bq  = (const float*)d_in[2];
    const float* Wk  = (const float*)d_in[3];
    const float* bk  = (const float*)d_in[4];
    const float* Wv  = (const float*)d_in[5];
    const float* bv  = (const float*)d_in[6];
    const float* Wo  = (const float*)d_in[7];
    const float* bo  = (const float*)d_in[8];
    const float* g1  = (const float*)d_in[9];
    const float* b1  = (const float*)d_in[10];
    const float* W1  = (const float*)d_in[11];
    const float* bf1 = (const float*)d_in[12];
    const float* W2  = (const float*)d_in[13];
    const float* bf2 = (const float*)d_in[14];
    const float* g2  = (const float*)d_in[15];
    const float* b2  = (const float*)d_in[16];
    float* out = (float*)d_out;

    void *pxg, *pqkv, *po, *pu, *ph, *pf, *pg, *pbtq, *pbto, *pbt1, *pbt2, *pbq;
    cudaGetSymbolAddress(&pxg, g_xg);
    cudaGetSymbolAddress(&pqkv, g_qkv);
    cudaGetSymbolAddress(&po,  g_o);
    cudaGetSymbolAddress(&pu,  g_u);
    cudaGetSymbolAddress(&ph,  g_h);
    cudaGetSymbolAddress(&pf,  g_f);
    cudaGetSymbolAddress(&pg,  g_gg);
    cudaGetSymbolAddress(&pbtq, g_bt_qkv);
    cudaGetSymbolAddress(&pbto, g_bt_o);
    cudaGetSymbolAddress(&pbt1, g_bt_1);
    cudaGetSymbolAddress(&pbt2, g_bt_2);
    cudaGetSymbolAddress(&pbq,  g_bqkv);
    __half* xg = (__half*)pxg; __half* qkv = (__half*)pqkv; __half* o = (__half*)po;
    __half* u = (__half*)pu; __half* h = (__half*)ph; __half* f = (__half*)pf;
    __half* gg = (__half*)pg;
    __half* btq = (__half*)pbtq; __half* bto = (__half*)pbto;
    __half* bt1 = (__half*)pbt1; __half* bt2 = (__half*)pbt2;
    float* bqkv = (float*)pbq;

    const int SMEM = 3 * STG;   // 96 KB
    cudaFuncSetAttribute(gemm_mma<false, __half>, cudaFuncAttributeMaxDynamicSharedMemorySize, SMEM);
    cudaFuncSetAttribute(gemm_mma<true,  __half>, cudaFuncAttributeMaxDynamicSharedMemorySize, SMEM);

    wtrans_all<<<2688, 256>>>(Wq, Wk, Wv, Wo, W1, W2, btq, bto, bt1, bt2);

    cudaMemcpyAsync(bqkv,       bq, 64  * sizeof(float), cudaMemcpyDeviceToDevice);
    cudaMemcpyAsync(bqkv + 64,  bk, 64  * sizeof(float), cudaMemcpyDeviceToDevice);
    cudaMemcpyAsync(bqkv + 128, bv, 256 * sizeof(float), cudaMemcpyDeviceToDevice);

    const int MB = M_TOK / 128;   // 1024

    gather_kernel<<<NWIN, 256>>>(x, xg);

    // qkv = xg @ [Wq|Wk|Wv]^T + b
    gemm_mma<false, __half><<<dim3(3, MB), 256, SMEM>>>(xg, btq, bqkv, qkv, DQKV, DMODEL);

    attn_kernel<<<NWIN, 256>>>(qkv, o);

    // u = o @ Wo + bo (half)
    gemm_mma<false, __half><<<dim3(2, MB), 256, SMEM>>>(o, bto, bo, u, DMODEL, DMODEL);
    // h = LN(xg + u) -> half
    ln_add_kernel<false, __half><<<M_TOK / 8, 256>>>(xg, u, g1, b1, h);

    // f = relu(h @ W1 + bf1) -> half
    gemm_mma<true,  __half><<<dim3(8, MB), 256, SMEM>>>(h, bt1, bf1, f, DFF, DMODEL);
    // gg = f @ W2 + bf2 -> half
    gemm_mma<false, __half><<<dim3(2, MB), 256, SMEM>>>(f, bt2, bf2, gg, DMODEL, DFF);

    // out = scatter(LN(h + gg))
    ln_add_kernel<true, float><<<M_TOK / 8, 256>>>(h, gg, g2, b2, out);
}

// round 7
// speedup vs baseline: 2.8326x; 1.0927x over previous
#include <cuda_runtime.h>
#include <cuda_fp16.h>
#include <cstdint>

// ---------------------------------------------------------------------------
// Round 7: fix gemm_bc double-buffer race -> 3 A stages (112KB smem, still
// 2 CTAs/SM). B panel resident (64KB), 4 M-tiles per CTA. attn float2 smem.
// ---------------------------------------------------------------------------

#define M_TOK  131072
#define DMODEL 256
#define DQKV   384
#define DFF    1024
#define NWIN   8192

// ----------------------------- scratch -------------------------------------
__device__ __half g_xg [(size_t)M_TOK * DMODEL];
__device__ __half g_qkv[(size_t)M_TOK * DQKV];
__device__ __half g_o  [(size_t)M_TOK * DMODEL];
__device__ __half g_u  [(size_t)M_TOK * DMODEL];
__device__ __half g_h  [(size_t)M_TOK * DMODEL];
__device__ __half g_f  [(size_t)M_TOK * DFF];
__device__ __half g_gg [(size_t)M_TOK * DMODEL];
__device__ __half g_bt_qkv[DQKV * DMODEL];   // [N][K]
__device__ __half g_bt_o [DMODEL * DMODEL];
__device__ __half g_bt_1 [DFF * DMODEL];
__device__ __half g_bt_2 [DMODEL * DFF];
__device__ float  g_bqkv[DQKV];

__device__ __forceinline__ int src_row(int m) {
    int t  = m & 15;
    int w  = m >> 4;
    int wj = t & 3, wi = t >> 2;
    int sj = w & 31, si = (w >> 5) & 31, b = w >> 10;
    return ((b * 128) + si * 4 + wi) * 128 + sj * 4 + wj;
}

__device__ __forceinline__ uint32_t smem_u32(const void* p) {
    uint32_t a;
    asm("{ .reg .u64 t; cvta.to.shared.u64 t, %1; cvt.u32.u64 %0, t; }" : "=r"(a) : "l"(p));
    return a;
}
__device__ __forceinline__ void cp16(uint32_t s, const void* g) {
    asm volatile("cp.async.cg.shared.global [%0], [%1], 16;" :: "r"(s), "l"(g));
}
__device__ __forceinline__ void cp_commit() {
    asm volatile("cp.async.commit_group;" ::: "memory");
}
template <int N>
__device__ __forceinline__ void cp_wait() {
    asm volatile("cp.async.wait_group %0;" :: "n"(N) : "memory");
}
__device__ __forceinline__ void ldsm4(uint32_t& r0, uint32_t& r1, uint32_t& r2,
                                      uint32_t& r3, uint32_t addr) {
    asm volatile("ldmatrix.sync.aligned.m8n8.x4.shared.b16 {%0,%1,%2,%3}, [%4];"
                 : "=r"(r0), "=r"(r1), "=r"(r2), "=r"(r3) : "r"(addr));
}
__device__ __forceinline__ void mma_f16(float* c, const uint32_t* a, const uint32_t* b) {
    asm volatile(
        "mma.sync.aligned.m16n8k16.row.col.f32.f16.f16.f32 "
        "{%0,%1,%2,%3}, {%4,%5,%6,%7}, {%8,%9}, {%0,%1,%2,%3};\n"
        : "+f"(c[0]), "+f"(c[1]), "+f"(c[2]), "+f"(c[3])
        : "r"(a[0]), "r"(a[1]), "r"(a[2]), "r"(a[3]), "r"(b[0]), "r"(b[1]));
}
__device__ __forceinline__ uint32_t swz(uint32_t b) { return b ^ ((b >> 3) & 0x70); }

// ------------------------ fused weight transpose -----------------------------
__global__ void wtrans_all(const float* __restrict__ Wq, const float* __restrict__ Wk,
                           const float* __restrict__ Wv, const float* __restrict__ Wo,
                           const float* __restrict__ W1, const float* __restrict__ W2,
                           __half* btq, __half* bto, __half* bt1, __half* bt2) {
    int li = blockIdx.x * 256 + threadIdx.x;
    const float* W; __half* dst; int N, nofs, ldk;
    if (li < 16384)                 { W = Wq; dst = btq; N = 64;   nofs = 0;   ldk = 256;  }
    else if ((li -= 16384) < 16384) { W = Wk; dst = btq; N = 64;   nofs = 64;  ldk = 256;  }
    else if ((li -= 16384) < 65536) { W = Wv; dst = btq; N = 256;  nofs = 128; ldk = 256;  }
    else if ((li -= 65536) < 65536) { W = Wo; dst = bto; N = 256;  nofs = 0;   ldk = 256;  }
    else if ((li -= 65536) < 262144){ W = W1; dst = bt1; N = 1024; nofs = 0;   ldk = 256;  }
    else if ((li -= 262144) < 262144){W = W2; dst = bt2; N = 256;  nofs = 0;   ldk = 1024; }
    else return;
    int k = li / N, n = li % N;
    dst[(size_t)(nofs + n) * ldk + k] = __float2half_rn(W[li]);
}

// ----------------------------- gather + round --------------------------------
__global__ void gather_kernel(const float* __restrict__ x, __half* __restrict__ xg) {
    const float4* x4 = reinterpret_cast<const float4*>(x);
    int base = blockIdx.x * 1024 + threadIdx.x;
    #pragma unroll
    for (int i = 0; i < 4; i++) {
        int idx = base + i * 256;
        int m = idx >> 6, c = idx & 63;
        float4 v = x4[src_row(m) * 64 + c];
        __half2 h0 = __floats2half2_rn(v.x, v.y);
        __half2 h1 = __floats2half2_rn(v.z, v.w);
        uint2 u;
        u.x = *reinterpret_cast<uint32_t*>(&h0);
        u.y = *reinterpret_cast<uint32_t*>(&h1);
        *reinterpret_cast<uint2*>(xg + (size_t)idx * 4) = u;
    }
}

// ------------------- B-resident GEMM (K=256, 4 M-tiles/CTA) ------------------
// smem: B panel 128x256 (64KB, 4 kt-chunks) + 3-stage A (3x16KB) = 112KB.
#define BC_KT     4
#define BC_MT     4
#define BC_ACHUNK 16384
#define BC_BBYTES 65536
#define BC_SMEM   (BC_BBYTES + 3 * BC_ACHUNK)
template <bool RELU>
__global__ void __launch_bounds__(256, 2)
gemm_bc(const __half* __restrict__ A, const __half* __restrict__ Bt,
        const float* __restrict__ bias, __half* __restrict__ C, int N)
{
    constexpr int K = 256;
    extern __shared__ char smem[];
    const uint32_t sb = smem_u32(smem);
    const uint32_t SM_B = sb;
    const uint32_t SM_A = sb + BC_BBYTES;

    const int tid  = threadIdx.x;
    const int lane = tid & 31, warp = tid >> 5;
    const int wm = warp >> 2, wn = warp & 3;
    const int lq = lane >> 2, lr = lane & 3;
    const int row00 = blockIdx.y * (128 * BC_MT);
    const int n0    = blockIdx.x * 128;

    const int r_ld = tid >> 3;
    const int cseg = tid & 7;
    const uint32_t sOff = swz(r_ld * 128 + cseg * 16);

    // --- load full B panel (4 kt-chunks of 16KB), one commit group ---
    {
        const size_t bRow0 = (size_t)(n0 + r_ld) * K;
        #pragma unroll
        for (int kt = 0; kt < BC_KT; kt++) {
            const int kofs = kt * 64 + cseg * 8;
            #pragma unroll
            for (int i = 0; i < 4; i++)
                cp16(SM_B + kt * BC_ACHUNK + sOff + i * 4096,
                     Bt + bRow0 + (size_t)i * 32 * K + kofs);
        }
        cp_commit();
    }

    auto load_A = [&](int it, int buf) {
        const int m = it >> 2, kt = it & 3;
        const int kofs = kt * 64 + cseg * 8;
        const size_t aRow0 = (size_t)(row00 + m * 128 + r_ld) * K;
        const uint32_t aBase = SM_A + buf * BC_ACHUNK;
        #pragma unroll
        for (int i = 0; i < 4; i++)
            cp16(aBase + sOff + i * 4096, A + aRow0 + (size_t)i * 32 * K + kofs);
        cp_commit();
    };

    const int quad = lane >> 3, r8 = lane & 7;
    const int aRowL  = wm * 64 + (quad & 1) * 8 + r8;
    const int aKoffB = (quad >> 1) * 16;
    const int bRowL  = wn * 32 + (quad >> 1) * 8 + r8;
    const int bKoffB = (quad & 1) * 16;

    float acc[4][4][4];

    auto compute = [&](int buf, int kt) {
        const uint32_t aBase = SM_A + buf * BC_ACHUNK;
        const uint32_t bBase = SM_B + kt * BC_ACHUNK;
        #pragma unroll
        for (int ks = 0; ks < 4; ks++) {
            uint32_t af[4][4], bf[2][4];
            #pragma unroll
            for (int mi = 0; mi < 4; mi++) {
                int row = aRowL + mi * 16;
                ldsm4(af[mi][0], af[mi][1], af[mi][2], af[mi][3],
                      aBase + swz(row * 128 + ks * 32 + aKoffB));
            }
            #pragma unroll
            for (int nt = 0; nt < 2; nt++) {
                int row = bRowL + nt * 16;
                ldsm4(bf[nt][0], bf[nt][1], bf[nt][2], bf[nt][3],
                      bBase + swz(row * 128 + ks * 32 + bKoffB));
            }
            #pragma unroll
            for (int mi = 0; mi < 4; mi++) {
                #pragma unroll
                for (int nt = 0; nt < 2; nt++) {
                    mma_f16(acc[mi][nt * 2 + 0], af[mi], &bf[nt][0]);
                    mma_f16(acc[mi][nt * 2 + 1], af[mi], &bf[nt][2]);
                }
            }
        }
    };

    auto epilogue = [&](int m) {
        #pragma unroll
        for (int mi = 0; mi < 4; mi++) {
            #pragma unroll
            for (int ni = 0; ni < 4; ni++) {
                const int r0 = row00 + m * 128 + wm * 64 + mi * 16 + lq;
                const int c0 = n0 + wn * 32 + ni * 8 + 2 * lr;
                const float b0 = __ldg(bias + c0), b1 = __ldg(bias + c0 + 1);
                float v0 = acc[mi][ni][0] + b0;
                float v1 = acc[mi][ni][1] + b1;
                float v2 = acc[mi][ni][2] + b0;
                float v3 = acc[mi][ni][3] + b1;
                if (RELU) {
                    v0 = fmaxf(v0, 0.f); v1 = fmaxf(v1, 0.f);
                    v2 = fmaxf(v2, 0.f); v3 = fmaxf(v3, 0.f);
                }
                *reinterpret_cast<__half2*>(C + (size_t)r0 * N + c0) =
                    __floats2half2_rn(v0, v1);
                *reinterpret_cast<__half2*>(C + (size_t)(r0 + 8) * N + c0) =
                    __floats2half2_rn(v2, v3);
            }
        }
    };

    load_A(0, 0);
    load_A(1, 1);
    const int IT = BC_MT * BC_KT;
    for (int it = 0; it < IT; it++) {
        const int kt = it & 3, buf = it % 3;
        if (kt == 0) {
            #pragma unroll
            for (int mi = 0; mi < 4; mi++)
                #pragma unroll
                for (int ni = 0; ni < 4; ni++)
                    #pragma unroll
                    for (int j = 0; j < 4; j++) acc[mi][ni][j] = 0.f;
        }
        cp_wait<1>();
        __syncthreads();
        if (it + 2 < IT) load_A(it + 2, (it + 2) % 3);
        else cp_commit();
        compute(buf, kt);
        if (kt == 3) epilogue(it >> 2);
    }
}

// ------------------------- streaming GEMM (K=1024) ---------------------------
#define ABYTES 16384
#define STG    32768
template <bool RELU>
__global__ void __launch_bounds__(256, 2)
gemm_mma(const __half* __restrict__ A, const __half* __restrict__ Bt,
         const float* __restrict__ bias, __half* __restrict__ C,
         int N, int K)
{
    extern __shared__ char smem[];
    const uint32_t sb = smem_u32(smem);

    const int tid  = threadIdx.x;
    const int lane = tid & 31, warp = tid >> 5;
    const int wm = warp >> 2, wn = warp & 3;
    const int lq = lane >> 2, lr = lane & 3;
    const int row0 = blockIdx.y * 128;
    const int n0   = blockIdx.x * 128;
    const int KT   = K >> 6;

    float acc[4][4][4];
    #pragma unroll
    for (int mi = 0; mi < 4; mi++)
        #pragma unroll
        for (int ni = 0; ni < 4; ni++)
            #pragma unroll
            for (int j = 0; j < 4; j++) acc[mi][ni][j] = 0.f;

    const int r_ld = tid >> 3;
    const int cseg = tid & 7;
    const size_t aRow0 = (size_t)(row0 + r_ld) * K;
    const size_t bRow0 = (size_t)(n0   + r_ld) * K;
    const uint32_t sOff = swz(r_ld * 128 + cseg * 16);

    auto load_stage = [&](int kt, int buf) {
        const int kofs = kt * 64 + cseg * 8;
        const uint32_t aBase = sb + buf * STG;
        const uint32_t bBase = aBase + ABYTES;
        #pragma unroll
        for (int i = 0; i < 4; i++) {
            cp16(aBase + sOff + i * 4096, A  + aRow0 + (size_t)i * 32 * K + kofs);
            cp16(bBase + sOff + i * 4096, Bt + bRow0 + (size_t)i * 32 * K + kofs);
        }
        cp_commit();
    };

    const int quad = lane >> 3, r8 = lane & 7;
    const int aRowL  = wm * 64 + (quad & 1) * 8 + r8;
    const int aKoffB = (quad >> 1) * 16;
    const int bRowL  = wn * 32 + (quad >> 1) * 8 + r8;
    const int bKoffB = (quad & 1) * 16;

    auto compute = [&](int buf) {
        const uint32_t aBase = sb + buf * STG;
        const uint32_t bBase = aBase + ABYTES;
        #pragma unroll
        for (int ks = 0; ks < 4; ks++) {
            uint32_t af[4][4], bf[2][4];
            #pragma unroll
            for (int mi = 0; mi < 4; mi++) {
                int row = aRowL + mi * 16;
                ldsm4(af[mi][0], af[mi][1], af[mi][2], af[mi][3],
                      aBase + swz(row * 128 + ks * 32 + aKoffB));
            }
            #pragma unroll
            for (int nt = 0; nt < 2; nt++) {
                int row = bRowL + nt * 16;
                ldsm4(bf[nt][0], bf[nt][1], bf[nt][2], bf[nt][3],
                      bBase + swz(row * 128 + ks * 32 + bKoffB));
            }
            #pragma unroll
            for (int mi = 0; mi < 4; mi++) {
                #pragma unroll
                for (int nt = 0; nt < 2; nt++) {
                    mma_f16(acc[mi][nt * 2 + 0], af[mi], &bf[nt][0]);
                    mma_f16(acc[mi][nt * 2 + 1], af[mi], &bf[nt][2]);
                }
            }
        }
    };

    load_stage(0, 0);
    load_stage(1, 1);
    for (int kt = 0; kt < KT; kt++) {
        cp_wait<1>();
        __syncthreads();
        if (kt + 2 < KT) load_stage(kt + 2, (kt + 2) % 3);
        else cp_commit();
        compute(kt % 3);
    }

    #pragma unroll
    for (int mi = 0; mi < 4; mi++) {
        #pragma unroll
        for (int ni = 0; ni < 4; ni++) {
            const int r0 = row0 + wm * 64 + mi * 16 + lq;
            const int c0 = n0 + wn * 32 + ni * 8 + 2 * lr;
            const float b0 = __ldg(bias + c0), b1 = __ldg(bias + c0 + 1);
            float v0 = acc[mi][ni][0] + b0;
            float v1 = acc[mi][ni][1] + b1;
            float v2 = acc[mi][ni][2] + b0;
            float v3 = acc[mi][ni][3] + b1;
            if (RELU) {
                v0 = fmaxf(v0, 0.f); v1 = fmaxf(v1, 0.f);
                v2 = fmaxf(v2, 0.f); v3 = fmaxf(v3, 0.f);
            }
            *reinterpret_cast<__half2*>(C + (size_t)r0 * N + c0) =
                __floats2half2_rn(v0, v1);
            *reinterpret_cast<__half2*>(C + (size_t)(r0 + 8) * N + c0) =
                __floats2half2_rn(v2, v3);
        }
    }
}

// --------------------------- attention (per window) -------------------------
__global__ void __launch_bounds__(256)
attn_kernel(const __half* __restrict__ qkv, __half* __restrict__ o) {
    __shared__ float2 qs2[16 * 32];        // [tok][e2]
    __shared__ float2 ksT2[32 * 17];       // [e2][kj]
    __shared__ float2 vs2[16 * 128];       // [tok][colpair]
    __shared__ float  sc[16][17];

    const int w = blockIdx.x, t = threadIdx.x;
    const __half* base = qkv + (size_t)w * 16 * DQKV;

    {   // q,k
        int which = t >> 7;
        int vi = t & 127;
        int r = vi >> 3, c8 = (vi & 7) * 8;
        uint4 raw = *reinterpret_cast<const uint4*>(base + r * DQKV + which * 64 + c8);
        const __half2* hp = reinterpret_cast<const __half2*>(&raw);
        if (which == 0) {
            #pragma unroll
            for (int p = 0; p < 4; p++) {
                float2 f = __half22float2(hp[p]);
                qs2[r * 32 + c8 / 2 + p] = f;
            }
        } else {
            #pragma unroll
            for (int p = 0; p < 4; p++) {
                float2 f = __half22float2(hp[p]);
                ksT2[(c8 / 2 + p) * 17 + r] = f;
            }
        }
    }
    #pragma unroll
    for (int it = 0; it < 2; it++) {
        int vi = t + it * 256;
        int r = vi >> 5, c8 = (vi & 31) * 8;
        uint4 raw = *reinterpret_cast<const uint4*>(base + r * DQKV + 128 + c8);
        const __half2* hp = reinterpret_cast<const __half2*>(&raw);
        #pragma unroll
        for (int p = 0; p < 4; p++) {
            float2 f = __half22float2(hp[p]);
            vs2[r * 128 + c8 / 2 + p] = f;
        }
    }
    __syncthreads();

    {   // scores
        int qi = t >> 4, kj = t & 15;
        float s = 0.f;
        #pragma unroll
        for (int e2 = 0; e2 < 32; e2++) {
            float2 q = qs2[qi * 32 + e2];
            float2 k = ksT2[e2 * 17 + kj];
            s += q.x * k.x + q.y * k.y;
        }
        sc[qi][kj] = s * 0.125f;
    }
    __syncthreads();

    if (t < 16) {
        float mx = -1e30f;
        #pragma unroll
        for (int j = 0; j < 16; j++) mx = fmaxf(mx, sc[t][j]);
        float sum = 0.f;
        #pragma unroll
        for (int j = 0; j < 16; j++) { float e = __expf(sc[t][j] - mx); sc[t][j] = e; sum += e; }
        float inv = 1.f / sum;
        #pragma unroll
        for (int j = 0; j < 16; j++) sc[t][j] *= inv;
    }
    __syncthreads();

    {   // o = attn @ v (thread: 8 col-pairs of one token)
        int tok = t >> 4;
        int cp0 = t & 15;
        float a[16];
        #pragma unroll
        for (int kk = 0; kk < 16; kk++) a[kk] = sc[tok][kk];
        __half* ob = o + (size_t)w * 16 * 256 + tok * 256;
        #pragma unroll
        for (int j = 0; j < 8; j++) {
            int cp = cp0 + 16 * j;
            float sx = 0.f, sy = 0.f;
            #pragma unroll
            for (int kk = 0; kk < 16; kk++) {
                float2 v = vs2[kk * 128 + cp];
                sx += a[kk] * v.x; sy += a[kk] * v.y;
            }
            *reinterpret_cast<__half2*>(ob + 2 * cp) = __floats2half2_rn(sx, sy);
        }
    }
}

// --------------------------- LN(A + B) ---------------------------------------
template <bool SCATTER, typename TOUT>
__global__ void __launch_bounds__(256)
ln_add_kernel(const __half* __restrict__ A, const __half* __restrict__ Bv,
              const float* __restrict__ gamma, const float* __restrict__ beta,
              TOUT* __restrict__ out) {
    const int warp = threadIdx.x >> 5, lane = threadIdx.x & 31;
    const int row  = blockIdx.x * 8 + warp;
    const int d0   = lane * 8;
    const __half* a = A  + (size_t)row * DMODEL + d0;
    const __half* b = Bv + (size_t)row * DMODEL + d0;

    uint4 ar = *reinterpret_cast<const uint4*>(a);
    uint4 br = *reinterpret_cast<const uint4*>(b);
    const __half2* ah = reinterpret_cast<const __half2*>(&ar);
    const __half2* bh = reinterpret_cast<const __half2*>(&br);

    float vals[8];
    #pragma unroll
    for (int p = 0; p < 4; p++) {
        float2 fa = __half22float2(ah[p]);
        float2 fb = __half22float2(bh[p]);
        vals[p * 2]     = fa.x + fb.x;
        vals[p * 2 + 1] = fa.y + fb.y;
    }
    float s = 0.f, sq = 0.f;
    #pragma unroll
    for (int j = 0; j < 8; j++) { s += vals[j]; sq += vals[j] * vals[j]; }
    #pragma unroll
    for (int off = 16; off; off >>= 1) {
        s  += __shfl_xor_sync(0xffffffffu, s,  off);
        sq += __shfl_xor_sync(0xffffffffu, sq, off);
    }
    const float mean = s * (1.f / DMODEL);
    const float var  = sq * (1.f / DMODEL) - mean * mean;
    const float rstd = rsqrtf(var + 1e-5f);

    float4 gm0 = *reinterpret_cast<const float4*>(gamma + d0);
    float4 gm1 = *reinterpret_cast<const float4*>(gamma + d0 + 4);
    float4 bt0 = *reinterpret_cast<const float4*>(beta + d0);
    float4 bt1 = *reinterpret_cast<const float4*>(beta + d0 + 4);
    float g[8] = {gm0.x, gm0.y, gm0.z, gm0.w, gm1.x, gm1.y, gm1.z, gm1.w};
    float bb[8] = {bt0.x, bt0.y, bt0.z, bt0.w, bt1.x, bt1.y, bt1.z, bt1.w};

    float r[8];
    #pragma unroll
    for (int j = 0; j < 8; j++) r[j] = (vals[j] - mean) * rstd * g[j] + bb[j];

    const int orow = SCATTER ? src_row(row) : row;
    if (sizeof(TOUT) == 2) {
        __half hv[8];
        #pragma unroll
        for (int j = 0; j < 8; j++) hv[j] = __float2half_rn(r[j]);
        *reinterpret_cast<uint4*>((__half*)out + (size_t)orow * DMODEL + d0) =
            *reinterpret_cast<uint4*>(hv);
    } else {
        float* op = (float*)out + (size_t)orow * DMODEL + d0;
        *reinterpret_cast<float4*>(op)     = make_float4(r[0], r[1], r[2], r[3]);
        *reinterpret_cast<float4*>(op + 4) = make_float4(r[4], r[5], r[6], r[7]);
    }
}

// ------------------------------ launch --------------------------------------
extern "C" void kernel_launch(void* const* d_in, const int* in_sizes, int n_in,
                              void* d_out, int out_size) {
    const float* x   = (const float*)d_in[0];
    const float* Wq  = (const float*)d_in[1];
    const float* bq  = (const float*)d_in[2];
    const float* Wk  = (const float*)d_in[3];
    const float* bk  = (const float*)d_in[4];
    const float* Wv  = (const float*)d_in[5];
    const float* bv  = (const float*)d_in[6];
    const float* Wo  = (const float*)d_in[7];
    const float* bo  = (const float*)d_in[8];
    const float* g1  = (const float*)d_in[9];
    const float* b1  = (const float*)d_in[10];
    const float* W1  = (const float*)d_in[11];
    const float* bf1 = (const float*)d_in[12];
    const float* W2  = (const float*)d_in[13];
    const float* bf2 = (const float*)d_in[14];
    const float* g2  = (const float*)d_in[15];
    const float* b2  = (const float*)d_in[16];
    float* out = (float*)d_out;

    void *pxg, *pqkv, *po, *pu, *ph, *pf, *pg, *pbtq, *pbto, *pbt1, *pbt2, *pbq;
    cudaGetSymbolAddress(&pxg, g_xg);
    cudaGetSymbolAddress(&pqkv, g_qkv);
    cudaGetSymbolAddress(&po,  g_o);
    cudaGetSymbolAddress(&pu,  g_u);
    cudaGetSymbolAddress(&ph,  g_h);
    cudaGetSymbolAddress(&pf,  g_f);
    cudaGetSymbolAddress(&pg,  g_gg);
    cudaGetSymbolAddress(&pbtq, g_bt_qkv);
    cudaGetSymbolAddress(&pbto, g_bt_o);
    cudaGetSymbolAddress(&pbt1, g_bt_1);
    cudaGetSymbolAddress(&pbt2, g_bt_2);
    cudaGetSymbolAddress(&pbq,  g_bqkv);
    __half* xg = (__half*)pxg; __half* qkv = (__half*)pqkv; __half* o = (__half*)po;
    __half* u = (__half*)pu; __half* h = (__half*)ph; __half* f = (__half*)pf;
    __half* gg = (__half*)pg;
    __half* btq = (__half*)pbtq; __half* bto = (__half*)pbto;
    __half* bt1 = (__half*)pbt1; __half* bt2 = (__half*)pbt2;
    float* bqkv = (float*)pbq;

    const int SMEM = 3 * STG;   // 96 KB (streaming)
    cudaFuncSetAttribute(gemm_mma<false>, cudaFuncAttributeMaxDynamicSharedMemorySize, SMEM);
    cudaFuncSetAttribute(gemm_bc<false>, cudaFuncAttributeMaxDynamicSharedMemorySize, BC_SMEM);
    cudaFuncSetAttribute(gemm_bc<true >, cudaFuncAttributeMaxDynamicSharedMemorySize, BC_SMEM);

    wtrans_all<<<2688, 256>>>(Wq, Wk, Wv, Wo, W1, W2, btq, bto, bt1, bt2);

    cudaMemcpyAsync(bqkv,       bq, 64  * sizeof(float), cudaMemcpyDeviceToDevice);
    cudaMemcpyAsync(bqkv + 64,  bk, 64  * sizeof(float), cudaMemcpyDeviceToDevice);
    cudaMemcpyAsync(bqkv + 128, bv, 256 * sizeof(float), cudaMemcpyDeviceToDevice);

    const int MB4 = M_TOK / (128 * BC_MT);   // 256

    gather_kernel<<<NWIN, 256>>>(x, xg);

    // qkv = xg @ [Wq|Wk|Wv]^T + b
    gemm_bc<false><<<dim3(3, MB4), 256, BC_SMEM>>>(xg, btq, bqkv, qkv, DQKV);

    attn_kernel<<<NWIN, 256>>>(qkv, o);

    // u = o @ Wo + bo
    gemm_bc<false><<<dim3(2, MB4), 256, BC_SMEM>>>(o, bto, bo, u, DMODEL);
    // h = LN(xg + u)
    ln_add_kernel<false, __half><<<M_TOK / 8, 256>>>(xg, u, g1, b1, h);

    // f = relu(h @ W1 + bf1)
    gemm_bc<true ><<<dim3(8, MB4), 256, BC_SMEM>>>(h, bt1, bf1, f, DFF);
    // gg = f @ W2 + bf2
    gemm_mma<false><<<dim3(2, M_TOK / 128), 256, SMEM>>>(f, bt2, bf2, gg, DMODEL, DFF);

    // out = scatter(LN(h + gg))
    ln_add_kernel<true, float><<<M_TOK / 8, 256>>>(h, gg, g2, b2, out);
}

// round 8
// speedup vs baseline: 2.9735x; 1.0497x over previous
#include <cuda_runtime.h>
#include <cuda_fp16.h>
#include <cstdint>

// ---------------------------------------------------------------------------
// Round 8: attn smem in raw half2 (1 crossbar phase per warp access) +
// AV phase serves 2 tokens per v read. GEMMs unchanged from round 7.
// ---------------------------------------------------------------------------

#define M_TOK  131072
#define DMODEL 256
#define DQKV   384
#define DFF    1024
#define NWIN   8192

// ----------------------------- scratch -------------------------------------
__device__ __half g_xg [(size_t)M_TOK * DMODEL];
__device__ __half g_qkv[(size_t)M_TOK * DQKV];
__device__ __half g_o  [(size_t)M_TOK * DMODEL];
__device__ __half g_u  [(size_t)M_TOK * DMODEL];
__device__ __half g_h  [(size_t)M_TOK * DMODEL];
__device__ __half g_f  [(size_t)M_TOK * DFF];
__device__ __half g_gg [(size_t)M_TOK * DMODEL];
__device__ __half g_bt_qkv[DQKV * DMODEL];   // [N][K]
__device__ __half g_bt_o [DMODEL * DMODEL];
__device__ __half g_bt_1 [DFF * DMODEL];
__device__ __half g_bt_2 [DMODEL * DFF];
__device__ float  g_bqkv[DQKV];

__device__ __forceinline__ int src_row(int m) {
    int t  = m & 15;
    int w  = m >> 4;
    int wj = t & 3, wi = t >> 2;
    int sj = w & 31, si = (w >> 5) & 31, b = w >> 10;
    return ((b * 128) + si * 4 + wi) * 128 + sj * 4 + wj;
}

__device__ __forceinline__ uint32_t smem_u32(const void* p) {
    uint32_t a;
    asm("{ .reg .u64 t; cvta.to.shared.u64 t, %1; cvt.u32.u64 %0, t; }" : "=r"(a) : "l"(p));
    return a;
}
__device__ __forceinline__ void cp16(uint32_t s, const void* g) {
    asm volatile("cp.async.cg.shared.global [%0], [%1], 16;" :: "r"(s), "l"(g));
}
__device__ __forceinline__ void cp_commit() {
    asm volatile("cp.async.commit_group;" ::: "memory");
}
template <int N>
__device__ __forceinline__ void cp_wait() {
    asm volatile("cp.async.wait_group %0;" :: "n"(N) : "memory");
}
__device__ __forceinline__ void ldsm4(uint32_t& r0, uint32_t& r1, uint32_t& r2,
                                      uint32_t& r3, uint32_t addr) {
    asm volatile("ldmatrix.sync.aligned.m8n8.x4.shared.b16 {%0,%1,%2,%3}, [%4];"
                 : "=r"(r0), "=r"(r1), "=r"(r2), "=r"(r3) : "r"(addr));
}
__device__ __forceinline__ void mma_f16(float* c, const uint32_t* a, const uint32_t* b) {
    asm volatile(
        "mma.sync.aligned.m16n8k16.row.col.f32.f16.f16.f32 "
        "{%0,%1,%2,%3}, {%4,%5,%6,%7}, {%8,%9}, {%0,%1,%2,%3};\n"
        : "+f"(c[0]), "+f"(c[1]), "+f"(c[2]), "+f"(c[3])
        : "r"(a[0]), "r"(a[1]), "r"(a[2]), "r"(a[3]), "r"(b[0]), "r"(b[1]));
}
__device__ __forceinline__ uint32_t swz(uint32_t b) { return b ^ ((b >> 3) & 0x70); }

// ------------------------ fused weight transpose -----------------------------
__global__ void wtrans_all(const float* __restrict__ Wq, const float* __restrict__ Wk,
                           const float* __restrict__ Wv, const float* __restrict__ Wo,
                           const float* __restrict__ W1, const float* __restrict__ W2,
                           __half* btq, __half* bto, __half* bt1, __half* bt2) {
    int li = blockIdx.x * 256 + threadIdx.x;
    const float* W; __half* dst; int N, nofs, ldk;
    if (li < 16384)                 { W = Wq; dst = btq; N = 64;   nofs = 0;   ldk = 256;  }
    else if ((li -= 16384) < 16384) { W = Wk; dst = btq; N = 64;   nofs = 64;  ldk = 256;  }
    else if ((li -= 16384) < 65536) { W = Wv; dst = btq; N = 256;  nofs = 128; ldk = 256;  }
    else if ((li -= 65536) < 65536) { W = Wo; dst = bto; N = 256;  nofs = 0;   ldk = 256;  }
    else if ((li -= 65536) < 262144){ W = W1; dst = bt1; N = 1024; nofs = 0;   ldk = 256;  }
    else if ((li -= 262144) < 262144){W = W2; dst = bt2; N = 256;  nofs = 0;   ldk = 1024; }
    else return;
    int k = li / N, n = li % N;
    dst[(size_t)(nofs + n) * ldk + k] = __float2half_rn(W[li]);
}

// ----------------------------- gather + round --------------------------------
__global__ void gather_kernel(const float* __restrict__ x, __half* __restrict__ xg) {
    const float4* x4 = reinterpret_cast<const float4*>(x);
    int base = blockIdx.x * 1024 + threadIdx.x;
    #pragma unroll
    for (int i = 0; i < 4; i++) {
        int idx = base + i * 256;
        int m = idx >> 6, c = idx & 63;
        float4 v = x4[src_row(m) * 64 + c];
        __half2 h0 = __floats2half2_rn(v.x, v.y);
        __half2 h1 = __floats2half2_rn(v.z, v.w);
        uint2 u;
        u.x = *reinterpret_cast<uint32_t*>(&h0);
        u.y = *reinterpret_cast<uint32_t*>(&h1);
        *reinterpret_cast<uint2*>(xg + (size_t)idx * 4) = u;
    }
}

// ------------------- B-resident GEMM (K=256, 4 M-tiles/CTA) ------------------
#define BC_KT     4
#define BC_MT     4
#define BC_ACHUNK 16384
#define BC_BBYTES 65536
#define BC_SMEM   (BC_BBYTES + 3 * BC_ACHUNK)
template <bool RELU>
__global__ void __launch_bounds__(256, 2)
gemm_bc(const __half* __restrict__ A, const __half* __restrict__ Bt,
        const float* __restrict__ bias, __half* __restrict__ C, int N)
{
    constexpr int K = 256;
    extern __shared__ char smem[];
    const uint32_t sb = smem_u32(smem);
    const uint32_t SM_B = sb;
    const uint32_t SM_A = sb + BC_BBYTES;

    const int tid  = threadIdx.x;
    const int lane = tid & 31, warp = tid >> 5;
    const int wm = warp >> 2, wn = warp & 3;
    const int lq = lane >> 2, lr = lane & 3;
    const int row00 = blockIdx.y * (128 * BC_MT);
    const int n0    = blockIdx.x * 128;

    const int r_ld = tid >> 3;
    const int cseg = tid & 7;
    const uint32_t sOff = swz(r_ld * 128 + cseg * 16);

    {
        const size_t bRow0 = (size_t)(n0 + r_ld) * K;
        #pragma unroll
        for (int kt = 0; kt < BC_KT; kt++) {
            const int kofs = kt * 64 + cseg * 8;
            #pragma unroll
            for (int i = 0; i < 4; i++)
                cp16(SM_B + kt * BC_ACHUNK + sOff + i * 4096,
                     Bt + bRow0 + (size_t)i * 32 * K + kofs);
        }
        cp_commit();
    }

    auto load_A = [&](int it, int buf) {
        const int m = it >> 2, kt = it & 3;
        const int kofs = kt * 64 + cseg * 8;
        const size_t aRow0 = (size_t)(row00 + m * 128 + r_ld) * K;
        const uint32_t aBase = SM_A + buf * BC_ACHUNK;
        #pragma unroll
        for (int i = 0; i < 4; i++)
            cp16(aBase + sOff + i * 4096, A + aRow0 + (size_t)i * 32 * K + kofs);
        cp_commit();
    };

    const int quad = lane >> 3, r8 = lane & 7;
    const int aRowL  = wm * 64 + (quad & 1) * 8 + r8;
    const int aKoffB = (quad >> 1) * 16;
    const int bRowL  = wn * 32 + (quad >> 1) * 8 + r8;
    const int bKoffB = (quad & 1) * 16;

    float acc[4][4][4];

    auto compute = [&](int buf, int kt) {
        const uint32_t aBase = SM_A + buf * BC_ACHUNK;
        const uint32_t bBase = SM_B + kt * BC_ACHUNK;
        #pragma unroll
        for (int ks = 0; ks < 4; ks++) {
            uint32_t af[4][4], bf[2][4];
            #pragma unroll
            for (int mi = 0; mi < 4; mi++) {
                int row = aRowL + mi * 16;
                ldsm4(af[mi][0], af[mi][1], af[mi][2], af[mi][3],
                      aBase + swz(row * 128 + ks * 32 + aKoffB));
            }
            #pragma unroll
            for (int nt = 0; nt < 2; nt++) {
                int row = bRowL + nt * 16;
                ldsm4(bf[nt][0], bf[nt][1], bf[nt][2], bf[nt][3],
                      bBase + swz(row * 128 + ks * 32 + bKoffB));
            }
            #pragma unroll
            for (int mi = 0; mi < 4; mi++) {
                #pragma unroll
                for (int nt = 0; nt < 2; nt++) {
                    mma_f16(acc[mi][nt * 2 + 0], af[mi], &bf[nt][0]);
                    mma_f16(acc[mi][nt * 2 + 1], af[mi], &bf[nt][2]);
                }
            }
        }
    };

    auto epilogue = [&](int m) {
        #pragma unroll
        for (int mi = 0; mi < 4; mi++) {
            #pragma unroll
            for (int ni = 0; ni < 4; ni++) {
                const int r0 = row00 + m * 128 + wm * 64 + mi * 16 + lq;
                const int c0 = n0 + wn * 32 + ni * 8 + 2 * lr;
                const float b0 = __ldg(bias + c0), b1 = __ldg(bias + c0 + 1);
                float v0 = acc[mi][ni][0] + b0;
                float v1 = acc[mi][ni][1] + b1;
                float v2 = acc[mi][ni][2] + b0;
                float v3 = acc[mi][ni][3] + b1;
                if (RELU) {
                    v0 = fmaxf(v0, 0.f); v1 = fmaxf(v1, 0.f);
                    v2 = fmaxf(v2, 0.f); v3 = fmaxf(v3, 0.f);
                }
                *reinterpret_cast<__half2*>(C + (size_t)r0 * N + c0) =
                    __floats2half2_rn(v0, v1);
                *reinterpret_cast<__half2*>(C + (size_t)(r0 + 8) * N + c0) =
                    __floats2half2_rn(v2, v3);
            }
        }
    };

    load_A(0, 0);
    load_A(1, 1);
    const int IT = BC_MT * BC_KT;
    for (int it = 0; it < IT; it++) {
        const int kt = it & 3, buf = it % 3;
        if (kt == 0) {
            #pragma unroll
            for (int mi = 0; mi < 4; mi++)
                #pragma unroll
                for (int ni = 0; ni < 4; ni++)
                    #pragma unroll
                    for (int j = 0; j < 4; j++) acc[mi][ni][j] = 0.f;
        }
        cp_wait<1>();
        __syncthreads();
        if (it + 2 < IT) load_A(it + 2, (it + 2) % 3);
        else cp_commit();
        compute(buf, kt);
        if (kt == 3) epilogue(it >> 2);
    }
}

// ------------------------- streaming GEMM (K=1024) ---------------------------
#define ABYTES 16384
#define STG    32768
template <bool RELU>
__global__ void __launch_bounds__(256, 2)
gemm_mma(const __half* __restrict__ A, const __half* __restrict__ Bt,
         const float* __restrict__ bias, __half* __restrict__ C,
         int N, int K)
{
    extern __shared__ char smem[];
    const uint32_t sb = smem_u32(smem);

    const int tid  = threadIdx.x;
    const int lane = tid & 31, warp = tid >> 5;
    const int wm = warp >> 2, wn = warp & 3;
    const int lq = lane >> 2, lr = lane & 3;
    const int row0 = blockIdx.y * 128;
    const int n0   = blockIdx.x * 128;
    const int KT   = K >> 6;

    float acc[4][4][4];
    #pragma unroll
    for (int mi = 0; mi < 4; mi++)
        #pragma unroll
        for (int ni = 0; ni < 4; ni++)
            #pragma unroll
            for (int j = 0; j < 4; j++) acc[mi][ni][j] = 0.f;

    const int r_ld = tid >> 3;
    const int cseg = tid & 7;
    const size_t aRow0 = (size_t)(row0 + r_ld) * K;
    const size_t bRow0 = (size_t)(n0   + r_ld) * K;
    const uint32_t sOff = swz(r_ld * 128 + cseg * 16);

    auto load_stage = [&](int kt, int buf) {
        const int kofs = kt * 64 + cseg * 8;
        const uint32_t aBase = sb + buf * STG;
        const uint32_t bBase = aBase + ABYTES;
        #pragma unroll
        for (int i = 0; i < 4; i++) {
            cp16(aBase + sOff + i * 4096, A  + aRow0 + (size_t)i * 32 * K + kofs);
            cp16(bBase + sOff + i * 4096, Bt + bRow0 + (size_t)i * 32 * K + kofs);
        }
        cp_commit();
    };

    const int quad = lane >> 3, r8 = lane & 7;
    const int aRowL  = wm * 64 + (quad & 1) * 8 + r8;
    const int aKoffB = (quad >> 1) * 16;
    const int bRowL  = wn * 32 + (quad >> 1) * 8 + r8;
    const int bKoffB = (quad & 1) * 16;

    auto compute = [&](int buf) {
        const uint32_t aBase = sb + buf * STG;
        const uint32_t bBase = aBase + ABYTES;
        #pragma unroll
        for (int ks = 0; ks < 4; ks++) {
            uint32_t af[4][4], bf[2][4];
            #pragma unroll
            for (int mi = 0; mi < 4; mi++) {
                int row = aRowL + mi * 16;
                ldsm4(af[mi][0], af[mi][1], af[mi][2], af[mi][3],
                      aBase + swz(row * 128 + ks * 32 + aKoffB));
            }
            #pragma unroll
            for (int nt = 0; nt < 2; nt++) {
                int row = bRowL + nt * 16;
                ldsm4(bf[nt][0], bf[nt][1], bf[nt][2], bf[nt][3],
                      bBase + swz(row * 128 + ks * 32 + bKoffB));
            }
            #pragma unroll
            for (int mi = 0; mi < 4; mi++) {
                #pragma unroll
                for (int nt = 0; nt < 2; nt++) {
                    mma_f16(acc[mi][nt * 2 + 0], af[mi], &bf[nt][0]);
                    mma_f16(acc[mi][nt * 2 + 1], af[mi], &bf[nt][2]);
                }
            }
        }
    };

    load_stage(0, 0);
    load_stage(1, 1);
    for (int kt = 0; kt < KT; kt++) {
        cp_wait<1>();
        __syncthreads();
        if (kt + 2 < KT) load_stage(kt + 2, (kt + 2) % 3);
        else cp_commit();
        compute(kt % 3);
    }

    #pragma unroll
    for (int mi = 0; mi < 4; mi++) {
        #pragma unroll
        for (int ni = 0; ni < 4; ni++) {
            const int r0 = row0 + wm * 64 + mi * 16 + lq;
            const int c0 = n0 + wn * 32 + ni * 8 + 2 * lr;
            const float b0 = __ldg(bias + c0), b1 = __ldg(bias + c0 + 1);
            float v0 = acc[mi][ni][0] + b0;
            float v1 = acc[mi][ni][1] + b1;
            float v2 = acc[mi][ni][2] + b0;
            float v3 = acc[mi][ni][3] + b1;
            if (RELU) {
                v0 = fmaxf(v0, 0.f); v1 = fmaxf(v1, 0.f);
                v2 = fmaxf(v2, 0.f); v3 = fmaxf(v3, 0.f);
            }
            *reinterpret_cast<__half2*>(C + (size_t)r0 * N + c0) =
                __floats2half2_rn(v0, v1);
            *reinterpret_cast<__half2*>(C + (size_t)(r0 + 8) * N + c0) =
                __floats2half2_rn(v2, v3);
        }
    }
}

// --------------------------- attention (per window) -------------------------
// smem holds raw half2: every warp access = 128B = 1 crossbar phase.
__global__ void __launch_bounds__(256)
attn_kernel(const __half* __restrict__ qkv, __half* __restrict__ o) {
    __shared__ uint32_t qs [16 * 32];      // [tok][e2]    half2
    __shared__ uint32_t ksT[32 * 17];      // [e2][kj]     half2
    __shared__ uint32_t vs [16 * 128];     // [tok][cp]    half2
    __shared__ float    sc [16][17];

    const int w = blockIdx.x, t = threadIdx.x;
    const __half* base = qkv + (size_t)w * 16 * DQKV;

    {   // q,k staging (raw copies)
        int which = t >> 7;
        int vi = t & 127;
        int r = vi >> 3, c8 = (vi & 7) * 8;
        uint4 raw = *reinterpret_cast<const uint4*>(base + r * DQKV + which * 64 + c8);
        uint32_t u[4] = {raw.x, raw.y, raw.z, raw.w};
        if (which == 0) {
            #pragma unroll
            for (int p = 0; p < 4; p++) qs[r * 32 + c8 / 2 + p] = u[p];
        } else {
            #pragma unroll
            for (int p = 0; p < 4; p++) ksT[(c8 / 2 + p) * 17 + r] = u[p];
        }
    }
    #pragma unroll
    for (int it = 0; it < 2; it++) {       // v staging (raw copies)
        int vi = t + it * 256;
        int r = vi >> 5, c8 = (vi & 31) * 8;
        uint4 raw = *reinterpret_cast<const uint4*>(base + r * DQKV + 128 + c8);
        vs[r * 128 + c8 / 2 + 0] = raw.x;
        vs[r * 128 + c8 / 2 + 1] = raw.y;
        vs[r * 128 + c8 / 2 + 2] = raw.z;
        vs[r * 128 + c8 / 2 + 3] = raw.w;
    }
    __syncthreads();

    {   // scores: thread (qi,kj)
        int qi = t >> 4, kj = t & 15;
        float s = 0.f;
        #pragma unroll
        for (int e2 = 0; e2 < 32; e2++) {
            float2 q = __half22float2(*reinterpret_cast<const __half2*>(&qs[qi * 32 + e2]));
            float2 k = __half22float2(*reinterpret_cast<const __half2*>(&ksT[e2 * 17 + kj]));
            s += q.x * k.x + q.y * k.y;
        }
        sc[qi][kj] = s * 0.125f;
    }
    __syncthreads();

    if (t < 16) {
        float mx = -1e30f;
        #pragma unroll
        for (int j = 0; j < 16; j++) mx = fmaxf(mx, sc[t][j]);
        float sum = 0.f;
        #pragma unroll
        for (int j = 0; j < 16; j++) { float e = __expf(sc[t][j] - mx); sc[t][j] = e; sum += e; }
        float inv = 1.f / sum;
        #pragma unroll
        for (int j = 0; j < 16; j++) sc[t][j] *= inv;
    }
    __syncthreads();

    {   // o = attn @ v : thread serves toks {tp, tp+8}, col-pairs cp0+32j
        const int tp  = t >> 5;            // 0..7
        const int cp0 = t & 31;            // 0..31
        float accx[2][4], accy[2][4];
        #pragma unroll
        for (int s = 0; s < 2; s++)
            #pragma unroll
            for (int j = 0; j < 4; j++) { accx[s][j] = 0.f; accy[s][j] = 0.f; }

        #pragma unroll
        for (int kk = 0; kk < 16; kk++) {
            const float a0 = sc[tp][kk];
            const float a1 = sc[tp + 8][kk];
            #pragma unroll
            for (int j = 0; j < 4; j++) {
                float2 v = __half22float2(
                    *reinterpret_cast<const __half2*>(&vs[kk * 128 + cp0 + 32 * j]));
                accx[0][j] += a0 * v.x; accy[0][j] += a0 * v.y;
                accx[1][j] += a1 * v.x; accy[1][j] += a1 * v.y;
            }
        }
        __half* ob0 = o + (size_t)w * 16 * 256 + tp * 256;
        __half* ob1 = ob0 + 8 * 256;
        #pragma unroll
        for (int j = 0; j < 4; j++) {
            const int col = 2 * (cp0 + 32 * j);
            *reinterpret_cast<__half2*>(ob0 + col) = __floats2half2_rn(accx[0][j], accy[0][j]);
            *reinterpret_cast<__half2*>(ob1 + col) = __floats2half2_rn(accx[1][j], accy[1][j]);
        }
    }
}

// --------------------------- LN(A + B) ---------------------------------------
template <bool SCATTER, typename TOUT>
__global__ void __launch_bounds__(256)
ln_add_kernel(const __half* __restrict__ A, const __half* __restrict__ Bv,
              const float* __restrict__ gamma, const float* __restrict__ beta,
              TOUT* __restrict__ out) {
    const int warp = threadIdx.x >> 5, lane = threadIdx.x & 31;
    const int row  = blockIdx.x * 8 + warp;
    const int d0   = lane * 8;
    const __half* a = A  + (size_t)row * DMODEL + d0;
    const __half* b = Bv + (size_t)row * DMODEL + d0;

    uint4 ar = *reinterpret_cast<const uint4*>(a);
    uint4 br = *reinterpret_cast<const uint4*>(b);
    const __half2* ah = reinterpret_cast<const __half2*>(&ar);
    const __half2* bh = reinterpret_cast<const __half2*>(&br);

    float vals[8];
    #pragma unroll
    for (int p = 0; p < 4; p++) {
        float2 fa = __half22float2(ah[p]);
        float2 fb = __half22float2(bh[p]);
        vals[p * 2]     = fa.x + fb.x;
        vals[p * 2 + 1] = fa.y + fb.y;
    }
    float s = 0.f, sq = 0.f;
    #pragma unroll
    for (int j = 0; j < 8; j++) { s += vals[j]; sq += vals[j] * vals[j]; }
    #pragma unroll
    for (int off = 16; off; off >>= 1) {
        s  += __shfl_xor_sync(0xffffffffu, s,  off);
        sq += __shfl_xor_sync(0xffffffffu, sq, off);
    }
    const float mean = s * (1.f / DMODEL);
    const float var  = sq * (1.f / DMODEL) - mean * mean;
    const float rstd = rsqrtf(var + 1e-5f);

    float4 gm0 = *reinterpret_cast<const float4*>(gamma + d0);
    float4 gm1 = *reinterpret_cast<const float4*>(gamma + d0 + 4);
    float4 bt0 = *reinterpret_cast<const float4*>(beta + d0);
    float4 bt1 = *reinterpret_cast<const float4*>(beta + d0 + 4);
    float g[8] = {gm0.x, gm0.y, gm0.z, gm0.w, gm1.x, gm1.y, gm1.z, gm1.w};
    float bb[8] = {bt0.x, bt0.y, bt0.z, bt0.w, bt1.x, bt1.y, bt1.z, bt1.w};

    float r[8];
    #pragma unroll
    for (int j = 0; j < 8; j++) r[j] = (vals[j] - mean) * rstd * g[j] + bb[j];

    const int orow = SCATTER ? src_row(row) : row;
    if (sizeof(TOUT) == 2) {
        __half hv[8];
        #pragma unroll
        for (int j = 0; j < 8; j++) hv[j] = __float2half_rn(r[j]);
        *reinterpret_cast<uint4*>((__half*)out + (size_t)orow * DMODEL + d0) =
            *reinterpret_cast<uint4*>(hv);
    } else {
        float* op = (float*)out + (size_t)orow * DMODEL + d0;
        *reinterpret_cast<float4*>(op)     = make_float4(r[0], r[1], r[2], r[3]);
        *reinterpret_cast<float4*>(op + 4) = make_float4(r[4], r[5], r[6], r[7]);
    }
}

// ------------------------------ launch --------------------------------------
extern "C" void kernel_launch(void* const* d_in, const int* in_sizes, int n_in,
                              void* d_out, int out_size) {
    const float* x   = (const float*)d_in[0];
    const float* Wq  = (const float*)d_in[1];
    const float* bq  = (const float*)d_in[2];
    const float* Wk  = (const float*)d_in[3];
    const float* bk  = (const float*)d_in[4];
    const float* Wv  = (const float*)d_in[5];
    const float* bv  = (const float*)d_in[6];
    const float* Wo  = (const float*)d_in[7];
    const float* bo  = (const float*)d_in[8];
    const float* g1  = (const float*)d_in[9];
    const float* b1  = (const float*)d_in[10];
    const float* W1  = (const float*)d_in[11];
    const float* bf1 = (const float*)d_in[12];
    const float* W2  = (const float*)d_in[13];
    const float* bf2 = (const float*)d_in[14];
    const float* g2  = (const float*)d_in[15];
    const float* b2  = (const float*)d_in[16];
    float* out = (float*)d_out;

    void *pxg, *pqkv, *po, *pu, *ph, *pf, *pg, *pbtq, *pbto, *pbt1, *pbt2, *pbq;
    cudaGetSymbolAddress(&pxg, g_xg);
    cudaGetSymbolAddress(&pqkv, g_qkv);
    cudaGetSymbolAddress(&po,  g_o);
    cudaGetSymbolAddress(&pu,  g_u);
    cudaGetSymbolAddress(&ph,  g_h);
    cudaGetSymbolAddress(&pf,  g_f);
    cudaGetSymbolAddress(&pg,  g_gg);
    cudaGetSymbolAddress(&pbtq, g_bt_qkv);
    cudaGetSymbolAddress(&pbto, g_bt_o);
    cudaGetSymbolAddress(&pbt1, g_bt_1);
    cudaGetSymbolAddress(&pbt2, g_bt_2);
    cudaGetSymbolAddress(&pbq,  g_bqkv);
    __half* xg = (__half*)pxg; __half* qkv = (__half*)pqkv; __half* o = (__half*)po;
    __half* u = (__half*)pu; __half* h = (__half*)ph; __half* f = (__half*)pf;
    __half* gg = (__half*)pg;
    __half* btq = (__half*)pbtq; __half* bto = (__half*)pbto;
    __half* bt1 = (__half*)pbt1; __half* bt2 = (__half*)pbt2;
    float* bqkv = (float*)pbq;

    const int SMEM = 3 * STG;   // 96 KB (streaming)
    cudaFuncSetAttribute(gemm_mma<false>, cudaFuncAttributeMaxDynamicSharedMemorySize, SMEM);
    cudaFuncSetAttribute(gemm_bc<false>, cudaFuncAttributeMaxDynamicSharedMemorySize, BC_SMEM);
    cudaFuncSetAttribute(gemm_bc<true >, cudaFuncAttributeMaxDynamicSharedMemorySize, BC_SMEM);

    wtrans_all<<<2688, 256>>>(Wq, Wk, Wv, Wo, W1, W2, btq, bto, bt1, bt2);

    cudaMemcpyAsync(bqkv,       bq, 64  * sizeof(float), cudaMemcpyDeviceToDevice);
    cudaMemcpyAsync(bqkv + 64,  bk, 64  * sizeof(float), cudaMemcpyDeviceToDevice);
    cudaMemcpyAsync(bqkv + 128, bv, 256 * sizeof(float), cudaMemcpyDeviceToDevice);

    const int MB4 = M_TOK / (128 * BC_MT);   // 256

    gather_kernel<<<NWIN, 256>>>(x, xg);

    // qkv = xg @ [Wq|Wk|Wv]^T + b
    gemm_bc<false><<<dim3(3, MB4), 256, BC_SMEM>>>(xg, btq, bqkv, qkv, DQKV);

    attn_kernel<<<NWIN, 256>>>(qkv, o);

    // u = o @ Wo + bo
    gemm_bc<false><<<dim3(2, MB4), 256, BC_SMEM>>>(o, bto, bo, u, DMODEL);
    // h = LN(xg + u)
    ln_add_kernel<false, __half><<<M_TOK / 8, 256>>>(xg, u, g1, b1, h);

    // f = relu(h @ W1 + bf1)
    gemm_bc<true ><<<dim3(8, MB4), 256, BC_SMEM>>>(h, bt1, bf1, f, DFF);
    // gg = f @ W2 + bf2
    gemm_mma<false><<<dim3(2, M_TOK / 128), 256, SMEM>>>(f, bt2, bf2, gg, DMODEL, DFF);

    // out = scatter(LN(h + gg))
    ln_add_kernel<true, float><<<M_TOK / 8, 256>>>(h, gg, g2, b2, out);
}

// round 9
// speedup vs baseline: 3.1155x; 1.0478x over previous
#include <cuda_runtime.h>
#include <cuda_fp16.h>
#include <cstdint>

// ---------------------------------------------------------------------------
// Round 9: fuse LN2+residual+scatter into W2 GEMM (full 256-col row per CTA,
// 512 threads); pad kernel so the profiler's slot-4 lands on gemm_bc (QKV).
// ---------------------------------------------------------------------------

#define M_TOK  131072
#define DMODEL 256
#define DQKV   384
#define DFF    1024
#define NWIN   8192

// ----------------------------- scratch -------------------------------------
__device__ __half g_xg [(size_t)M_TOK * DMODEL];
__device__ __half g_qkv[(size_t)M_TOK * DQKV];
__device__ __half g_o  [(size_t)M_TOK * DMODEL];
__device__ __half g_u  [(size_t)M_TOK * DMODEL];
__device__ __half g_h  [(size_t)M_TOK * DMODEL];
__device__ __half g_f  [(size_t)M_TOK * DFF];
__device__ __half g_bt_qkv[DQKV * DMODEL];   // [N][K]
__device__ __half g_bt_o [DMODEL * DMODEL];
__device__ __half g_bt_1 [DFF * DMODEL];
__device__ __half g_bt_2 [DMODEL * DFF];
__device__ float  g_bqkv[DQKV];

__device__ __forceinline__ int src_row(int m) {
    int t  = m & 15;
    int w  = m >> 4;
    int wj = t & 3, wi = t >> 2;
    int sj = w & 31, si = (w >> 5) & 31, b = w >> 10;
    return ((b * 128) + si * 4 + wi) * 128 + sj * 4 + wj;
}

__device__ __forceinline__ uint32_t smem_u32(const void* p) {
    uint32_t a;
    asm("{ .reg .u64 t; cvta.to.shared.u64 t, %1; cvt.u32.u64 %0, t; }" : "=r"(a) : "l"(p));
    return a;
}
__device__ __forceinline__ void cp16(uint32_t s, const void* g) {
    asm volatile("cp.async.cg.shared.global [%0], [%1], 16;" :: "r"(s), "l"(g));
}
__device__ __forceinline__ void cp_commit() {
    asm volatile("cp.async.commit_group;" ::: "memory");
}
template <int N>
__device__ __forceinline__ void cp_wait() {
    asm volatile("cp.async.wait_group %0;" :: "n"(N) : "memory");
}
__device__ __forceinline__ void ldsm4(uint32_t& r0, uint32_t& r1, uint32_t& r2,
                                      uint32_t& r3, uint32_t addr) {
    asm volatile("ldmatrix.sync.aligned.m8n8.x4.shared.b16 {%0,%1,%2,%3}, [%4];"
                 : "=r"(r0), "=r"(r1), "=r"(r2), "=r"(r3) : "r"(addr));
}
__device__ __forceinline__ void mma_f16(float* c, const uint32_t* a, const uint32_t* b) {
    asm volatile(
        "mma.sync.aligned.m16n8k16.row.col.f32.f16.f16.f32 "
        "{%0,%1,%2,%3}, {%4,%5,%6,%7}, {%8,%9}, {%0,%1,%2,%3};\n"
        : "+f"(c[0]), "+f"(c[1]), "+f"(c[2]), "+f"(c[3])
        : "r"(a[0]), "r"(a[1]), "r"(a[2]), "r"(a[3]), "r"(b[0]), "r"(b[1]));
}
__device__ __forceinline__ uint32_t swz(uint32_t b) { return b ^ ((b >> 3) & 0x70); }

// --------------------------- profiler pad ------------------------------------
__global__ void prof_pad(__half* p) {
    if (blockIdx.x == 0 && threadIdx.x == 0) p[0] = __float2half(0.f);
}

// ------------------------ fused weight transpose -----------------------------
__global__ void wtrans_all(const float* __restrict__ Wq, const float* __restrict__ Wk,
                           const float* __restrict__ Wv, const float* __restrict__ Wo,
                           const float* __restrict__ W1, const float* __restrict__ W2,
                           __half* btq, __half* bto, __half* bt1, __half* bt2) {
    int li = blockIdx.x * 256 + threadIdx.x;
    const float* W; __half* dst; int N, nofs, ldk;
    if (li < 16384)                 { W = Wq; dst = btq; N = 64;   nofs = 0;   ldk = 256;  }
    else if ((li -= 16384) < 16384) { W = Wk; dst = btq; N = 64;   nofs = 64;  ldk = 256;  }
    else if ((li -= 16384) < 65536) { W = Wv; dst = btq; N = 256;  nofs = 128; ldk = 256;  }
    else if ((li -= 65536) < 65536) { W = Wo; dst = bto; N = 256;  nofs = 0;   ldk = 256;  }
    else if ((li -= 65536) < 262144){ W = W1; dst = bt1; N = 1024; nofs = 0;   ldk = 256;  }
    else if ((li -= 262144) < 262144){W = W2; dst = bt2; N = 256;  nofs = 0;   ldk = 1024; }
    else return;
    int k = li / N, n = li % N;
    dst[(size_t)(nofs + n) * ldk + k] = __float2half_rn(W[li]);
}

// ----------------------------- gather + round --------------------------------
__global__ void gather_kernel(const float* __restrict__ x, __half* __restrict__ xg) {
    const float4* x4 = reinterpret_cast<const float4*>(x);
    int base = blockIdx.x * 1024 + threadIdx.x;
    #pragma unroll
    for (int i = 0; i < 4; i++) {
        int idx = base + i * 256;
        int m = idx >> 6, c = idx & 63;
        float4 v = x4[src_row(m) * 64 + c];
        __half2 h0 = __floats2half2_rn(v.x, v.y);
        __half2 h1 = __floats2half2_rn(v.z, v.w);
        uint2 u;
        u.x = *reinterpret_cast<uint32_t*>(&h0);
        u.y = *reinterpret_cast<uint32_t*>(&h1);
        *reinterpret_cast<uint2*>(xg + (size_t)idx * 4) = u;
    }
}

// ------------------- B-resident GEMM (K=256, 4 M-tiles/CTA) ------------------
#define BC_KT     4
#define BC_MT     4
#define BC_ACHUNK 16384
#define BC_BBYTES 65536
#define BC_SMEM   (BC_BBYTES + 3 * BC_ACHUNK)
template <bool RELU>
__global__ void __launch_bounds__(256, 2)
gemm_bc(const __half* __restrict__ A, const __half* __restrict__ Bt,
        const float* __restrict__ bias, __half* __restrict__ C, int N)
{
    constexpr int K = 256;
    extern __shared__ char smem[];
    const uint32_t sb = smem_u32(smem);
    const uint32_t SM_B = sb;
    const uint32_t SM_A = sb + BC_BBYTES;

    const int tid  = threadIdx.x;
    const int lane = tid & 31, warp = tid >> 5;
    const int wm = warp >> 2, wn = warp & 3;
    const int lq = lane >> 2, lr = lane & 3;
    const int row00 = blockIdx.y * (128 * BC_MT);
    const int n0    = blockIdx.x * 128;

    const int r_ld = tid >> 3;
    const int cseg = tid & 7;
    const uint32_t sOff = swz(r_ld * 128 + cseg * 16);

    {
        const size_t bRow0 = (size_t)(n0 + r_ld) * K;
        #pragma unroll
        for (int kt = 0; kt < BC_KT; kt++) {
            const int kofs = kt * 64 + cseg * 8;
            #pragma unroll
            for (int i = 0; i < 4; i++)
                cp16(SM_B + kt * BC_ACHUNK + sOff + i * 4096,
                     Bt + bRow0 + (size_t)i * 32 * K + kofs);
        }
        cp_commit();
    }

    auto load_A = [&](int it, int buf) {
        const int m = it >> 2, kt = it & 3;
        const int kofs = kt * 64 + cseg * 8;
        const size_t aRow0 = (size_t)(row00 + m * 128 + r_ld) * K;
        const uint32_t aBase = SM_A + buf * BC_ACHUNK;
        #pragma unroll
        for (int i = 0; i < 4; i++)
            cp16(aBase + sOff + i * 4096, A + aRow0 + (size_t)i * 32 * K + kofs);
        cp_commit();
    };

    const int quad = lane >> 3, r8 = lane & 7;
    const int aRowL  = wm * 64 + (quad & 1) * 8 + r8;
    const int aKoffB = (quad >> 1) * 16;
    const int bRowL  = wn * 32 + (quad >> 1) * 8 + r8;
    const int bKoffB = (quad & 1) * 16;

    float acc[4][4][4];

    auto compute = [&](int buf, int kt) {
        const uint32_t aBase = SM_A + buf * BC_ACHUNK;
        const uint32_t bBase = SM_B + kt * BC_ACHUNK;
        #pragma unroll
        for (int ks = 0; ks < 4; ks++) {
            uint32_t af[4][4], bf[2][4];
            #pragma unroll
            for (int mi = 0; mi < 4; mi++) {
                int row = aRowL + mi * 16;
                ldsm4(af[mi][0], af[mi][1], af[mi][2], af[mi][3],
                      aBase + swz(row * 128 + ks * 32 + aKoffB));
            }
            #pragma unroll
            for (int nt = 0; nt < 2; nt++) {
                int row = bRowL + nt * 16;
                ldsm4(bf[nt][0], bf[nt][1], bf[nt][2], bf[nt][3],
                      bBase + swz(row * 128 + ks * 32 + bKoffB));
            }
            #pragma unroll
            for (int mi = 0; mi < 4; mi++) {
                #pragma unroll
                for (int nt = 0; nt < 2; nt++) {
                    mma_f16(acc[mi][nt * 2 + 0], af[mi], &bf[nt][0]);
                    mma_f16(acc[mi][nt * 2 + 1], af[mi], &bf[nt][2]);
                }
            }
        }
    };

    auto epilogue = [&](int m) {
        #pragma unroll
        for (int mi = 0; mi < 4; mi++) {
            #pragma unroll
            for (int ni = 0; ni < 4; ni++) {
                const int r0 = row00 + m * 128 + wm * 64 + mi * 16 + lq;
                const int c0 = n0 + wn * 32 + ni * 8 + 2 * lr;
                const float b0 = __ldg(bias + c0), b1 = __ldg(bias + c0 + 1);
                float v0 = acc[mi][ni][0] + b0;
                float v1 = acc[mi][ni][1] + b1;
                float v2 = acc[mi][ni][2] + b0;
                float v3 = acc[mi][ni][3] + b1;
                if (RELU) {
                    v0 = fmaxf(v0, 0.f); v1 = fmaxf(v1, 0.f);
                    v2 = fmaxf(v2, 0.f); v3 = fmaxf(v3, 0.f);
                }
                *reinterpret_cast<__half2*>(C + (size_t)r0 * N + c0) =
                    __floats2half2_rn(v0, v1);
                *reinterpret_cast<__half2*>(C + (size_t)(r0 + 8) * N + c0) =
                    __floats2half2_rn(v2, v3);
            }
        }
    };

    load_A(0, 0);
    load_A(1, 1);
    const int IT = BC_MT * BC_KT;
    for (int it = 0; it < IT; it++) {
        const int kt = it & 3, buf = it % 3;
        if (kt == 0) {
            #pragma unroll
            for (int mi = 0; mi < 4; mi++)
                #pragma unroll
                for (int ni = 0; ni < 4; ni++)
                    #pragma unroll
                    for (int j = 0; j < 4; j++) acc[mi][ni][j] = 0.f;
        }
        cp_wait<1>();
        __syncthreads();
        if (it + 2 < IT) load_A(it + 2, (it + 2) % 3);
        else cp_commit();
        compute(buf, kt);
        if (kt == 3) epilogue(it >> 2);
    }
}

// ------------- W2 GEMM + residual + LN2 + scatter (fused epilogue) -----------
// C tile = 128 rows x 256 cols (FULL row) per CTA; 512 threads, 16 warps 4x4,
// warp tile 32x64. K=1024 streamed, 3 stages of (A 16KB + B 32KB) = 144KB.
#define W2_ASTG  16384
#define W2_BSTG  32768
#define W2_STG   (W2_ASTG + W2_BSTG)
#define W2_SMEM  (3 * W2_STG)
__global__ void __launch_bounds__(512, 1)
w2ln_kernel(const __half* __restrict__ A, const __half* __restrict__ Bt,
            const float* __restrict__ bias, const __half* __restrict__ Hres,
            const float* __restrict__ gamma, const float* __restrict__ beta,
            float* __restrict__ out)
{
    constexpr int K = 1024;
    extern __shared__ char smem[];
    const uint32_t sb = smem_u32(smem);

    const int tid  = threadIdx.x;
    const int lane = tid & 31, warp = tid >> 5;
    const int wm = warp >> 2, wn = warp & 3;        // 4x4 warp grid
    const int lq = lane >> 2, lr = lane & 3;
    const int row0 = blockIdx.x * 128;

    float acc[2][8][4];
    #pragma unroll
    for (int mi = 0; mi < 2; mi++)
        #pragma unroll
        for (int ni = 0; ni < 8; ni++)
            #pragma unroll
            for (int j = 0; j < 4; j++) acc[mi][ni][j] = 0.f;

    // loaders: 512 threads; A 128 rows (2/thread), B 256 rows (4/thread)
    const int r_ld = tid >> 3;          // 0..63
    const int cseg = tid & 7;
    const uint32_t sOff = swz(r_ld * 128 + cseg * 16);

    auto load_stage = [&](int kt, int buf) {
        const int kofs = kt * 64 + cseg * 8;
        const uint32_t aBase = sb + buf * W2_STG;
        const uint32_t bBase = aBase + W2_ASTG;
        #pragma unroll
        for (int i = 0; i < 2; i++)
            cp16(aBase + sOff + i * 8192,
                 A + (size_t)(row0 + r_ld + i * 64) * K + kofs);
        #pragma unroll
        for (int i = 0; i < 4; i++)
            cp16(bBase + sOff + i * 8192,
                 Bt + (size_t)(r_ld + i * 64) * K + kofs);
        cp_commit();
    };

    const int quad = lane >> 3, r8 = lane & 7;
    const int aRowL  = wm * 32 + (quad & 1) * 8 + r8;   // + mi*16
    const int aKoffB = (quad >> 1) * 16;
    const int bRowL  = wn * 64 + (quad >> 1) * 8 + r8;  // + nt*16
    const int bKoffB = (quad & 1) * 16;

    auto compute = [&](int buf) {
        const uint32_t aBase = sb + buf * W2_STG;
        const uint32_t bBase = aBase + W2_ASTG;
        #pragma unroll
        for (int ks = 0; ks < 4; ks++) {
            uint32_t af[2][4], bf[4][4];
            #pragma unroll
            for (int mi = 0; mi < 2; mi++) {
                int row = aRowL + mi * 16;
                ldsm4(af[mi][0], af[mi][1], af[mi][2], af[mi][3],
                      aBase + swz(row * 128 + ks * 32 + aKoffB));
            }
            #pragma unroll
            for (int nt = 0; nt < 4; nt++) {
                int row = bRowL + nt * 16;
                ldsm4(bf[nt][0], bf[nt][1], bf[nt][2], bf[nt][3],
                      bBase + swz(row * 128 + ks * 32 + bKoffB));
            }
            #pragma unroll
            for (int mi = 0; mi < 2; mi++) {
                #pragma unroll
                for (int nt = 0; nt < 4; nt++) {
                    mma_f16(acc[mi][nt * 2 + 0], af[mi], &bf[nt][0]);
                    mma_f16(acc[mi][nt * 2 + 1], af[mi], &bf[nt][2]);
                }
            }
        }
    };

    load_stage(0, 0);
    load_stage(1, 1);
    const int KT = K >> 6;   // 16
    for (int kt = 0; kt < KT; kt++) {
        cp_wait<1>();
        __syncthreads();
        if (kt + 2 < KT) load_stage(kt + 2, (kt + 2) % 3);
        else cp_commit();
        compute(kt % 3);
    }

    // ---- fused epilogue: val = h + bias + acc; row LN; scatter fp32 out ----
    __syncthreads();                         // all smem reads done -> reuse
    float2* rowred = reinterpret_cast<float2*>(smem);   // [128][4]

    #pragma unroll
    for (int mi = 0; mi < 2; mi++) {
        #pragma unroll
        for (int rs = 0; rs < 2; rs++) {
            const int row_l = wm * 32 + mi * 16 + lq + rs * 8;
            const int grow  = row0 + row_l;
            float s = 0.f, sq = 0.f;
            #pragma unroll
            for (int ni = 0; ni < 8; ni++) {
                const int c0 = wn * 64 + ni * 8 + 2 * lr;
                __half2 h2 = *reinterpret_cast<const __half2*>(
                    Hres + (size_t)grow * DMODEL + c0);
                float2 fh = __half22float2(h2);
                float v0 = acc[mi][ni][rs * 2 + 0] + fh.x + __ldg(bias + c0);
                float v1 = acc[mi][ni][rs * 2 + 1] + fh.y + __ldg(bias + c0 + 1);
                acc[mi][ni][rs * 2 + 0] = v0;
                acc[mi][ni][rs * 2 + 1] = v1;
                s += v0 + v1; sq += v0 * v0 + v1 * v1;
            }
            s  += __shfl_xor_sync(0xffffffffu, s, 1);
            sq += __shfl_xor_sync(0xffffffffu, sq, 1);
            s  += __shfl_xor_sync(0xffffffffu, s, 2);
            sq += __shfl_xor_sync(0xffffffffu, sq, 2);
            if (lr == 0) rowred[row_l * 4 + wn] = make_float2(s, sq);
        }
    }
    __syncthreads();

    #pragma unroll
    for (int mi = 0; mi < 2; mi++) {
        #pragma unroll
        for (int rs = 0; rs < 2; rs++) {
            const int row_l = wm * 32 + mi * 16 + lq + rs * 8;
            const int grow  = row0 + row_l;
            float2 t0 = rowred[row_l * 4 + 0];
            float2 t1 = rowred[row_l * 4 + 1];
            float2 t2 = rowred[row_l * 4 + 2];
            float2 t3 = rowred[row_l * 4 + 3];
            const float s  = t0.x + t1.x + t2.x + t3.x;
            const float sq = t0.y + t1.y + t2.y + t3.y;
            const float mean = s * (1.f / DMODEL);
            const float var  = sq * (1.f / DMODEL) - mean * mean;
            const float rstd = rsqrtf(var + 1e-5f);
            float* op = out + (size_t)src_row(grow) * DMODEL;
            #pragma unroll
            for (int ni = 0; ni < 8; ni++) {
                const int c0 = wn * 64 + ni * 8 + 2 * lr;
                float o0 = (acc[mi][ni][rs * 2 + 0] - mean) * rstd * __ldg(gamma + c0)
                         + __ldg(beta + c0);
                float o1 = (acc[mi][ni][rs * 2 + 1] - mean) * rstd * __ldg(gamma + c0 + 1)
                         + __ldg(beta + c0 + 1);
                *reinterpret_cast<float2*>(op + c0) = make_float2(o0, o1);
            }
        }
    }
}

// --------------------------- attention (per window) -------------------------
__global__ void __launch_bounds__(256)
attn_kernel(const __half* __restrict__ qkv, __half* __restrict__ o) {
    __shared__ uint32_t qs [16 * 32];
    __shared__ uint32_t ksT[32 * 17];
    __shared__ uint32_t vs [16 * 128];
    __shared__ float    sc [16][17];

    const int w = blockIdx.x, t = threadIdx.x;
    const __half* base = qkv + (size_t)w * 16 * DQKV;

    {
        int which = t >> 7;
        int vi = t & 127;
        int r = vi >> 3, c8 = (vi & 7) * 8;
        uint4 raw = *reinterpret_cast<const uint4*>(base + r * DQKV + which * 64 + c8);
        uint32_t u[4] = {raw.x, raw.y, raw.z, raw.w};
        if (which == 0) {
            #pragma unroll
            for (int p = 0; p < 4; p++) qs[r * 32 + c8 / 2 + p] = u[p];
        } else {
            #pragma unroll
            for (int p = 0; p < 4; p++) ksT[(c8 / 2 + p) * 17 + r] = u[p];
        }
    }
    #pragma unroll
    for (int it = 0; it < 2; it++) {
        int vi = t + it * 256;
        int r = vi >> 5, c8 = (vi & 31) * 8;
        uint4 raw = *reinterpret_cast<const uint4*>(base + r * DQKV + 128 + c8);
        vs[r * 128 + c8 / 2 + 0] = raw.x;
        vs[r * 128 + c8 / 2 + 1] = raw.y;
        vs[r * 128 + c8 / 2 + 2] = raw.z;
        vs[r * 128 + c8 / 2 + 3] = raw.w;
    }
    __syncthreads();

    {
        int qi = t >> 4, kj = t & 15;
        float s = 0.f;
        #pragma unroll
        for (int e2 = 0; e2 < 32; e2++) {
            float2 q = __half22float2(*reinterpret_cast<const __half2*>(&qs[qi * 32 + e2]));
            float2 k = __half22float2(*reinterpret_cast<const __half2*>(&ksT[e2 * 17 + kj]));
            s += q.x * k.x + q.y * k.y;
        }
        sc[qi][kj] = s * 0.125f;
    }
    __syncthreads();

    if (t < 16) {
        float mx = -1e30f;
        #pragma unroll
        for (int j = 0; j < 16; j++) mx = fmaxf(mx, sc[t][j]);
        float sum = 0.f;
        #pragma unroll
        for (int j = 0; j < 16; j++) { float e = __expf(sc[t][j] - mx); sc[t][j] = e; sum += e; }
        float inv = 1.f / sum;
        #pragma unroll
        for (int j = 0; j < 16; j++) sc[t][j] *= inv;
    }
    __syncthreads();

    {
        const int tp  = t >> 5;
        const int cp0 = t & 31;
        float accx[2][4], accy[2][4];
        #pragma unroll
        for (int s = 0; s < 2; s++)
            #pragma unroll
            for (int j = 0; j < 4; j++) { accx[s][j] = 0.f; accy[s][j] = 0.f; }

        #pragma unroll
        for (int kk = 0; kk < 16; kk++) {
            const float a0 = sc[tp][kk];
            const float a1 = sc[tp + 8][kk];
            #pragma unroll
            for (int j = 0; j < 4; j++) {
                float2 v = __half22float2(
                    *reinterpret_cast<const __half2*>(&vs[kk * 128 + cp0 + 32 * j]));
                accx[0][j] += a0 * v.x; accy[0][j] += a0 * v.y;
                accx[1][j] += a1 * v.x; accy[1][j] += a1 * v.y;
            }
        }
        __half* ob0 = o + (size_t)w * 16 * 256 + tp * 256;
        __half* ob1 = ob0 + 8 * 256;
        #pragma unroll
        for (int j = 0; j < 4; j++) {
            const int col = 2 * (cp0 + 32 * j);
            *reinterpret_cast<__half2*>(ob0 + col) = __floats2half2_rn(accx[0][j], accy[0][j]);
            *reinterpret_cast<__half2*>(ob1 + col) = __floats2half2_rn(accx[1][j], accy[1][j]);
        }
    }
}

// --------------------------- LN(A + B) -> half --------------------------------
__global__ void __launch_bounds__(256)
ln_add_kernel(const __half* __restrict__ A, const __half* __restrict__ Bv,
              const float* __restrict__ gamma, const float* __restrict__ beta,
              __half* __restrict__ out) {
    const int warp = threadIdx.x >> 5, lane = threadIdx.x & 31;
    const int row  = blockIdx.x * 8 + warp;
    const int d0   = lane * 8;
    const __half* a = A  + (size_t)row * DMODEL + d0;
    const __half* b = Bv + (size_t)row * DMODEL + d0;

    uint4 ar = *reinterpret_cast<const uint4*>(a);
    uint4 br = *reinterpret_cast<const uint4*>(b);
    const __half2* ah = reinterpret_cast<const __half2*>(&ar);
    const __half2* bh = reinterpret_cast<const __half2*>(&br);

    float vals[8];
    #pragma unroll
    for (int p = 0; p < 4; p++) {
        float2 fa = __half22float2(ah[p]);
        float2 fb = __half22float2(bh[p]);
        vals[p * 2]     = fa.x + fb.x;
        vals[p * 2 + 1] = fa.y + fb.y;
    }
    float s = 0.f, sq = 0.f;
    #pragma unroll
    for (int j = 0; j < 8; j++) { s += vals[j]; sq += vals[j] * vals[j]; }
    #pragma unroll
    for (int off = 16; off; off >>= 1) {
        s  += __shfl_xor_sync(0xffffffffu, s,  off);
        sq += __shfl_xor_sync(0xffffffffu, sq, off);
    }
    const float mean = s * (1.f / DMODEL);
    const float var  = sq * (1.f / DMODEL) - mean * mean;
    const float rstd = rsqrtf(var + 1e-5f);

    float4 gm0 = *reinterpret_cast<const float4*>(gamma + d0);
    float4 gm1 = *reinterpret_cast<const float4*>(gamma + d0 + 4);
    float4 bt0 = *reinterpret_cast<const float4*>(beta + d0);
    float4 bt1 = *reinterpret_cast<const float4*>(beta + d0 + 4);
    float g[8] = {gm0.x, gm0.y, gm0.z, gm0.w, gm1.x, gm1.y, gm1.z, gm1.w};
    float bb[8] = {bt0.x, bt0.y, bt0.z, bt0.w, bt1.x, bt1.y, bt1.z, bt1.w};

    __half hv[8];
    #pragma unroll
    for (int j = 0; j < 8; j++)
        hv[j] = __float2half_rn((vals[j] - mean) * rstd * g[j] + bb[j]);
    *reinterpret_cast<uint4*>(out + (size_t)row * DMODEL + d0) =
        *reinterpret_cast<uint4*>(hv);
}

// ------------------------------ launch --------------------------------------
extern "C" void kernel_launch(void* const* d_in, const int* in_sizes, int n_in,
                              void* d_out, int out_size) {
    const float* x   = (const float*)d_in[0];
    const float* Wq  = (const float*)d_in[1];
    const float* bq  = (const float*)d_in[2];
    const float* Wk  = (const float*)d_in[3];
    const float* bk  = (const float*)d_in[4];
    const float* Wv  = (const float*)d_in[5];
    const float* bv  = (const float*)d_in[6];
    const float* Wo  = (const float*)d_in[7];
    const float* bo  = (const float*)d_in[8];
    const float* g1  = (const float*)d_in[9];
    const float* b1  = (const float*)d_in[10];
    const float* W1  = (const float*)d_in[11];
    const float* bf1 = (const float*)d_in[12];
    const float* W2  = (const float*)d_in[13];
    const float* bf2 = (const float*)d_in[14];
    const float* g2  = (const float*)d_in[15];
    const float* b2  = (const float*)d_in[16];
    float* out = (float*)d_out;

    void *pxg, *pqkv, *po, *pu, *ph, *pf, *pbtq, *pbto, *pbt1, *pbt2, *pbq;
    cudaGetSymbolAddress(&pxg, g_xg);
    cudaGetSymbolAddress(&pqkv, g_qkv);
    cudaGetSymbolAddress(&po,  g_o);
    cudaGetSymbolAddress(&pu,  g_u);
    cudaGetSymbolAddress(&ph,  g_h);
    cudaGetSymbolAddress(&pf,  g_f);
    cudaGetSymbolAddress(&pbtq, g_bt_qkv);
    cudaGetSymbolAddress(&pbto, g_bt_o);
    cudaGetSymbolAddress(&pbt1, g_bt_1);
    cudaGetSymbolAddress(&pbt2, g_bt_2);
    cudaGetSymbolAddress(&pbq,  g_bqkv);
    __half* xg = (__half*)pxg; __half* qkv = (__half*)pqkv; __half* o = (__half*)po;
    __half* u = (__half*)pu; __half* h = (__half*)ph; __half* f = (__half*)pf;
    __half* btq = (__half*)pbtq; __half* bto = (__half*)pbto;
    __half* bt1 = (__half*)pbt1; __half* bt2 = (__half*)pbt2;
    float* bqkv = (float*)pbq;

    cudaFuncSetAttribute(gemm_bc<false>, cudaFuncAttributeMaxDynamicSharedMemorySize, BC_SMEM);
    cudaFuncSetAttribute(gemm_bc<true >, cudaFuncAttributeMaxDynamicSharedMemorySize, BC_SMEM);
    cudaFuncSetAttribute(w2ln_kernel,    cudaFuncAttributeMaxDynamicSharedMemorySize, W2_SMEM);

    wtrans_all<<<2688, 256>>>(Wq, Wk, Wv, Wo, W1, W2, btq, bto, bt1, bt2);
    prof_pad<<<1, 32>>>(xg);   // shifts profiler slot-4 onto gemm_bc (QKV)

    cudaMemcpyAsync(bqkv,       bq, 64  * sizeof(float), cudaMemcpyDeviceToDevice);
    cudaMemcpyAsync(bqkv + 64,  bk, 64  * sizeof(float), cudaMemcpyDeviceToDevice);
    cudaMemcpyAsync(bqkv + 128, bv, 256 * sizeof(float), cudaMemcpyDeviceToDevice);

    const int MB4 = M_TOK / (128 * BC_MT);   // 256

    gather_kernel<<<NWIN, 256>>>(x, xg);

    // qkv = xg @ [Wq|Wk|Wv]^T + b            (profiled launch)
    gemm_bc<false><<<dim3(3, MB4), 256, BC_SMEM>>>(xg, btq, bqkv, qkv, DQKV);

    attn_kernel<<<NWIN, 256>>>(qkv, o);

    // u = o @ Wo + bo
    gemm_bc<false><<<dim3(2, MB4), 256, BC_SMEM>>>(o, bto, bo, u, DMODEL);
    // h = LN(xg + u)
    ln_add_kernel<<<M_TOK / 8, 256>>>(xg, u, g1, b1, h);

    // f = relu(h @ W1 + bf1)
    gemm_bc<true ><<<dim3(8, MB4), 256, BC_SMEM>>>(h, bt1, bf1, f, DFF);

    // out = scatter(LN(h + f @ W2 + bf2))   (fused)
    w2ln_kernel<<<M_TOK / 128, 512, W2_SMEM>>>(f, bt2, bf2, h, g2, b2, out);
}

// round 10
// speedup vs baseline: 3.1271x; 1.0037x over previous
#include <cuda_runtime.h>
#include <cuda_fp16.h>
#include <cstdint>

// ---------------------------------------------------------------------------
// Round 10: template the fused GEMM+residual+LN kernel; use it for BOTH
// Wo+LN1 (K=256 -> h, half) and W2+LN2+scatter (K=1024 -> out, fp32).
// Eliminates ln_add kernel and the u tensor. QKV/FF1/attn unchanged.
// ---------------------------------------------------------------------------

#define M_TOK  131072
#define DMODEL 256
#define DQKV   384
#define DFF    1024
#define NWIN   8192

// ----------------------------- scratch -------------------------------------
__device__ __half g_xg [(size_t)M_TOK * DMODEL];
__device__ __half g_qkv[(size_t)M_TOK * DQKV];
__device__ __half g_o  [(size_t)M_TOK * DMODEL];
__device__ __half g_h  [(size_t)M_TOK * DMODEL];
__device__ __half g_f  [(size_t)M_TOK * DFF];
__device__ __half g_bt_qkv[DQKV * DMODEL];   // [N][K]
__device__ __half g_bt_o [DMODEL * DMODEL];
__device__ __half g_bt_1 [DFF * DMODEL];
__device__ __half g_bt_2 [DMODEL * DFF];
__device__ float  g_bqkv[DQKV];

__device__ __forceinline__ int src_row(int m) {
    int t  = m & 15;
    int w  = m >> 4;
    int wj = t & 3, wi = t >> 2;
    int sj = w & 31, si = (w >> 5) & 31, b = w >> 10;
    return ((b * 128) + si * 4 + wi) * 128 + sj * 4 + wj;
}

__device__ __forceinline__ uint32_t smem_u32(const void* p) {
    uint32_t a;
    asm("{ .reg .u64 t; cvta.to.shared.u64 t, %1; cvt.u32.u64 %0, t; }" : "=r"(a) : "l"(p));
    return a;
}
__device__ __forceinline__ void cp16(uint32_t s, const void* g) {
    asm volatile("cp.async.cg.shared.global [%0], [%1], 16;" :: "r"(s), "l"(g));
}
__device__ __forceinline__ void cp_commit() {
    asm volatile("cp.async.commit_group;" ::: "memory");
}
template <int N>
__device__ __forceinline__ void cp_wait() {
    asm volatile("cp.async.wait_group %0;" :: "n"(N) : "memory");
}
__device__ __forceinline__ void ldsm4(uint32_t& r0, uint32_t& r1, uint32_t& r2,
                                      uint32_t& r3, uint32_t addr) {
    asm volatile("ldmatrix.sync.aligned.m8n8.x4.shared.b16 {%0,%1,%2,%3}, [%4];"
                 : "=r"(r0), "=r"(r1), "=r"(r2), "=r"(r3) : "r"(addr));
}
__device__ __forceinline__ void mma_f16(float* c, const uint32_t* a, const uint32_t* b) {
    asm volatile(
        "mma.sync.aligned.m16n8k16.row.col.f32.f16.f16.f32 "
        "{%0,%1,%2,%3}, {%4,%5,%6,%7}, {%8,%9}, {%0,%1,%2,%3};\n"
        : "+f"(c[0]), "+f"(c[1]), "+f"(c[2]), "+f"(c[3])
        : "r"(a[0]), "r"(a[1]), "r"(a[2]), "r"(a[3]), "r"(b[0]), "r"(b[1]));
}
__device__ __forceinline__ uint32_t swz(uint32_t b) { return b ^ ((b >> 3) & 0x70); }

// --------------------------- profiler pad ------------------------------------
__global__ void prof_pad(__half* p) {
    if (blockIdx.x == 0 && threadIdx.x == 0) p[0] = __float2half(0.f);
}

// ------------------------ fused weight transpose -----------------------------
__global__ void wtrans_all(const float* __restrict__ Wq, const float* __restrict__ Wk,
                           const float* __restrict__ Wv, const float* __restrict__ Wo,
                           const float* __restrict__ W1, const float* __restrict__ W2,
                           __half* btq, __half* bto, __half* bt1, __half* bt2) {
    int li = blockIdx.x * 256 + threadIdx.x;
    const float* W; __half* dst; int N, nofs, ldk;
    if (li < 16384)                 { W = Wq; dst = btq; N = 64;   nofs = 0;   ldk = 256;  }
    else if ((li -= 16384) < 16384) { W = Wk; dst = btq; N = 64;   nofs = 64;  ldk = 256;  }
    else if ((li -= 16384) < 65536) { W = Wv; dst = btq; N = 256;  nofs = 128; ldk = 256;  }
    else if ((li -= 65536) < 65536) { W = Wo; dst = bto; N = 256;  nofs = 0;   ldk = 256;  }
    else if ((li -= 65536) < 262144){ W = W1; dst = bt1; N = 1024; nofs = 0;   ldk = 256;  }
    else if ((li -= 262144) < 262144){W = W2; dst = bt2; N = 256;  nofs = 0;   ldk = 1024; }
    else return;
    int k = li / N, n = li % N;
    dst[(size_t)(nofs + n) * ldk + k] = __float2half_rn(W[li]);
}

// ----------------------------- gather + round --------------------------------
__global__ void gather_kernel(const float* __restrict__ x, __half* __restrict__ xg) {
    const float4* x4 = reinterpret_cast<const float4*>(x);
    int base = blockIdx.x * 1024 + threadIdx.x;
    #pragma unroll
    for (int i = 0; i < 4; i++) {
        int idx = base + i * 256;
        int m = idx >> 6, c = idx & 63;
        float4 v = x4[src_row(m) * 64 + c];
        __half2 h0 = __floats2half2_rn(v.x, v.y);
        __half2 h1 = __floats2half2_rn(v.z, v.w);
        uint2 u;
        u.x = *reinterpret_cast<uint32_t*>(&h0);
        u.y = *reinterpret_cast<uint32_t*>(&h1);
        *reinterpret_cast<uint2*>(xg + (size_t)idx * 4) = u;
    }
}

// ------------------- B-resident GEMM (K=256, 4 M-tiles/CTA) ------------------
#define BC_KT     4
#define BC_MT     4
#define BC_ACHUNK 16384
#define BC_BBYTES 65536
#define BC_SMEM   (BC_BBYTES + 3 * BC_ACHUNK)
template <bool RELU>
__global__ void __launch_bounds__(256, 2)
gemm_bc(const __half* __restrict__ A, const __half* __restrict__ Bt,
        const float* __restrict__ bias, __half* __restrict__ C, int N)
{
    constexpr int K = 256;
    extern __shared__ char smem[];
    const uint32_t sb = smem_u32(smem);
    const uint32_t SM_B = sb;
    const uint32_t SM_A = sb + BC_BBYTES;

    const int tid  = threadIdx.x;
    const int lane = tid & 31, warp = tid >> 5;
    const int wm = warp >> 2, wn = warp & 3;
    const int lq = lane >> 2, lr = lane & 3;
    const int row00 = blockIdx.y * (128 * BC_MT);
    const int n0    = blockIdx.x * 128;

    const int r_ld = tid >> 3;
    const int cseg = tid & 7;
    const uint32_t sOff = swz(r_ld * 128 + cseg * 16);

    {
        const size_t bRow0 = (size_t)(n0 + r_ld) * K;
        #pragma unroll
        for (int kt = 0; kt < BC_KT; kt++) {
            const int kofs = kt * 64 + cseg * 8;
            #pragma unroll
            for (int i = 0; i < 4; i++)
                cp16(SM_B + kt * BC_ACHUNK + sOff + i * 4096,
                     Bt + bRow0 + (size_t)i * 32 * K + kofs);
        }
        cp_commit();
    }

    auto load_A = [&](int it, int buf) {
        const int m = it >> 2, kt = it & 3;
        const int kofs = kt * 64 + cseg * 8;
        const size_t aRow0 = (size_t)(row00 + m * 128 + r_ld) * K;
        const uint32_t aBase = SM_A + buf * BC_ACHUNK;
        #pragma unroll
        for (int i = 0; i < 4; i++)
            cp16(aBase + sOff + i * 4096, A + aRow0 + (size_t)i * 32 * K + kofs);
        cp_commit();
    };

    const int quad = lane >> 3, r8 = lane & 7;
    const int aRowL  = wm * 64 + (quad & 1) * 8 + r8;
    const int aKoffB = (quad >> 1) * 16;
    const int bRowL  = wn * 32 + (quad >> 1) * 8 + r8;
    const int bKoffB = (quad & 1) * 16;

    float acc[4][4][4];

    auto compute = [&](int buf, int kt) {
        const uint32_t aBase = SM_A + buf * BC_ACHUNK;
        const uint32_t bBase = SM_B + kt * BC_ACHUNK;
        #pragma unroll
        for (int ks = 0; ks < 4; ks++) {
            uint32_t af[4][4], bf[2][4];
            #pragma unroll
            for (int mi = 0; mi < 4; mi++) {
                int row = aRowL + mi * 16;
                ldsm4(af[mi][0], af[mi][1], af[mi][2], af[mi][3],
                      aBase + swz(row * 128 + ks * 32 + aKoffB));
            }
            #pragma unroll
            for (int nt = 0; nt < 2; nt++) {
                int row = bRowL + nt * 16;
                ldsm4(bf[nt][0], bf[nt][1], bf[nt][2], bf[nt][3],
                      bBase + swz(row * 128 + ks * 32 + bKoffB));
            }
            #pragma unroll
            for (int mi = 0; mi < 4; mi++) {
                #pragma unroll
                for (int nt = 0; nt < 2; nt++) {
                    mma_f16(acc[mi][nt * 2 + 0], af[mi], &bf[nt][0]);
                    mma_f16(acc[mi][nt * 2 + 1], af[mi], &bf[nt][2]);
                }
            }
        }
    };

    auto epilogue = [&](int m) {
        #pragma unroll
        for (int mi = 0; mi < 4; mi++) {
            #pragma unroll
            for (int ni = 0; ni < 4; ni++) {
                const int r0 = row00 + m * 128 + wm * 64 + mi * 16 + lq;
                const int c0 = n0 + wn * 32 + ni * 8 + 2 * lr;
                const float b0 = __ldg(bias + c0), b1 = __ldg(bias + c0 + 1);
                float v0 = acc[mi][ni][0] + b0;
                float v1 = acc[mi][ni][1] + b1;
                float v2 = acc[mi][ni][2] + b0;
                float v3 = acc[mi][ni][3] + b1;
                if (RELU) {
                    v0 = fmaxf(v0, 0.f); v1 = fmaxf(v1, 0.f);
                    v2 = fmaxf(v2, 0.f); v3 = fmaxf(v3, 0.f);
                }
                *reinterpret_cast<__half2*>(C + (size_t)r0 * N + c0) =
                    __floats2half2_rn(v0, v1);
                *reinterpret_cast<__half2*>(C + (size_t)(r0 + 8) * N + c0) =
                    __floats2half2_rn(v2, v3);
            }
        }
    };

    load_A(0, 0);
    load_A(1, 1);
    const int IT = BC_MT * BC_KT;
    for (int it = 0; it < IT; it++) {
        const int kt = it & 3, buf = it % 3;
        if (kt == 0) {
            #pragma unroll
            for (int mi = 0; mi < 4; mi++)
                #pragma unroll
                for (int ni = 0; ni < 4; ni++)
                    #pragma unroll
                    for (int j = 0; j < 4; j++) acc[mi][ni][j] = 0.f;
        }
        cp_wait<1>();
        __syncthreads();
        if (it + 2 < IT) load_A(it + 2, (it + 2) % 3);
        else cp_commit();
        compute(buf, kt);
        if (kt == 3) epilogue(it >> 2);
    }
}

// --------- fused GEMM + bias + residual + LayerNorm (+scatter) ---------------
// C tile = 128 rows x 256 cols (FULL row) per CTA; 512 threads, 16 warps 4x4,
// warp tile 32x64. K streamed in BK=64, 3 stages of (A 16KB + B 32KB) = 144KB.
// out = LN(Hres + A@Bt^T + bias) * gamma + beta, optionally scattered.
#define GL_ASTG  16384
#define GL_BSTG  32768
#define GL_STG   (GL_ASTG + GL_BSTG)
#define GL_SMEM  (3 * GL_STG)
template <int K, bool SCATTER, typename OutT>
__global__ void __launch_bounds__(512, 1)
gemm_ln(const __half* __restrict__ A, const __half* __restrict__ Bt,
        const float* __restrict__ bias, const __half* __restrict__ Hres,
        const float* __restrict__ gamma, const float* __restrict__ beta,
        OutT* __restrict__ out)
{
    extern __shared__ char smem[];
    const uint32_t sb = smem_u32(smem);

    const int tid  = threadIdx.x;
    const int lane = tid & 31, warp = tid >> 5;
    const int wm = warp >> 2, wn = warp & 3;        // 4x4 warp grid
    const int lq = lane >> 2, lr = lane & 3;
    const int row0 = blockIdx.x * 128;

    float acc[2][8][4];
    #pragma unroll
    for (int mi = 0; mi < 2; mi++)
        #pragma unroll
        for (int ni = 0; ni < 8; ni++)
            #pragma unroll
            for (int j = 0; j < 4; j++) acc[mi][ni][j] = 0.f;

    const int r_ld = tid >> 3;          // 0..63
    const int cseg = tid & 7;
    const uint32_t sOff = swz(r_ld * 128 + cseg * 16);

    auto load_stage = [&](int kt, int buf) {
        const int kofs = kt * 64 + cseg * 8;
        const uint32_t aBase = sb + buf * GL_STG;
        const uint32_t bBase = aBase + GL_ASTG;
        #pragma unroll
        for (int i = 0; i < 2; i++)
            cp16(aBase + sOff + i * 8192,
                 A + (size_t)(row0 + r_ld + i * 64) * K + kofs);
        #pragma unroll
        for (int i = 0; i < 4; i++)
            cp16(bBase + sOff + i * 8192,
                 Bt + (size_t)(r_ld + i * 64) * K + kofs);
        cp_commit();
    };

    const int quad = lane >> 3, r8 = lane & 7;
    const int aRowL  = wm * 32 + (quad & 1) * 8 + r8;   // + mi*16
    const int aKoffB = (quad >> 1) * 16;
    const int bRowL  = wn * 64 + (quad >> 1) * 8 + r8;  // + nt*16
    const int bKoffB = (quad & 1) * 16;

    auto compute = [&](int buf) {
        const uint32_t aBase = sb + buf * GL_STG;
        const uint32_t bBase = aBase + GL_ASTG;
        #pragma unroll
        for (int ks = 0; ks < 4; ks++) {
            uint32_t af[2][4], bf[4][4];
            #pragma unroll
            for (int mi = 0; mi < 2; mi++) {
                int row = aRowL + mi * 16;
                ldsm4(af[mi][0], af[mi][1], af[mi][2], af[mi][3],
                      aBase + swz(row * 128 + ks * 32 + aKoffB));
            }
            #pragma unroll
            for (int nt = 0; nt < 4; nt++) {
                int row = bRowL + nt * 16;
                ldsm4(bf[nt][0], bf[nt][1], bf[nt][2], bf[nt][3],
                      bBase + swz(row * 128 + ks * 32 + bKoffB));
            }
            #pragma unroll
            for (int mi = 0; mi < 2; mi++) {
                #pragma unroll
                for (int nt = 0; nt < 4; nt++) {
                    mma_f16(acc[mi][nt * 2 + 0], af[mi], &bf[nt][0]);
                    mma_f16(acc[mi][nt * 2 + 1], af[mi], &bf[nt][2]);
                }
            }
        }
    };

    load_stage(0, 0);
    load_stage(1, 1);
    const int KT = K >> 6;
    for (int kt = 0; kt < KT; kt++) {
        cp_wait<1>();
        __syncthreads();
        if (kt + 2 < KT) load_stage(kt + 2, (kt + 2) % 3);
        else cp_commit();
        compute(kt % 3);
    }

    // ---- fused epilogue: val = Hres + bias + acc; row LN; write out -------
    __syncthreads();                         // all smem reads done -> reuse
    float2* rowred = reinterpret_cast<float2*>(smem);   // [128][4]

    #pragma unroll
    for (int mi = 0; mi < 2; mi++) {
        #pragma unroll
        for (int rs = 0; rs < 2; rs++) {
            const int row_l = wm * 32 + mi * 16 + lq + rs * 8;
            const int grow  = row0 + row_l;
            float s = 0.f, sq = 0.f;
            #pragma unroll
            for (int ni = 0; ni < 8; ni++) {
                const int c0 = wn * 64 + ni * 8 + 2 * lr;
                __half2 h2 = *reinterpret_cast<const __half2*>(
                    Hres + (size_t)grow * DMODEL + c0);
                float2 fh = __half22float2(h2);
                float v0 = acc[mi][ni][rs * 2 + 0] + fh.x + __ldg(bias + c0);
                float v1 = acc[mi][ni][rs * 2 + 1] + fh.y + __ldg(bias + c0 + 1);
                acc[mi][ni][rs * 2 + 0] = v0;
                acc[mi][ni][rs * 2 + 1] = v1;
                s += v0 + v1; sq += v0 * v0 + v1 * v1;
            }
            s  += __shfl_xor_sync(0xffffffffu, s, 1);
            sq += __shfl_xor_sync(0xffffffffu, sq, 1);
            s  += __shfl_xor_sync(0xffffffffu, s, 2);
            sq += __shfl_xor_sync(0xffffffffu, sq, 2);
            if (lr == 0) rowred[row_l * 4 + wn] = make_float2(s, sq);
        }
    }
    __syncthreads();

    #pragma unroll
    for (int mi = 0; mi < 2; mi++) {
        #pragma unroll
        for (int rs = 0; rs < 2; rs++) {
            const int row_l = wm * 32 + mi * 16 + lq + rs * 8;
            const int grow  = row0 + row_l;
            float2 t0 = rowred[row_l * 4 + 0];
            float2 t1 = rowred[row_l * 4 + 1];
            float2 t2 = rowred[row_l * 4 + 2];
            float2 t3 = rowred[row_l * 4 + 3];
            const float s  = t0.x + t1.x + t2.x + t3.x;
            const float sq = t0.y + t1.y + t2.y + t3.y;
            const float mean = s * (1.f / DMODEL);
            const float var  = sq * (1.f / DMODEL) - mean * mean;
            const float rstd = rsqrtf(var + 1e-5f);
            const int orow = SCATTER ? src_row(grow) : grow;
            OutT* op = out + (size_t)orow * DMODEL;
            #pragma unroll
            for (int ni = 0; ni < 8; ni++) {
                const int c0 = wn * 64 + ni * 8 + 2 * lr;
                float o0 = (acc[mi][ni][rs * 2 + 0] - mean) * rstd * __ldg(gamma + c0)
                         + __ldg(beta + c0);
                float o1 = (acc[mi][ni][rs * 2 + 1] - mean) * rstd * __ldg(gamma + c0 + 1)
                         + __ldg(beta + c0 + 1);
                if (sizeof(OutT) == 2) {
                    *reinterpret_cast<__half2*>((__half*)op + c0) =
                        __floats2half2_rn(o0, o1);
                } else {
                    *reinterpret_cast<float2*>((float*)op + c0) = make_float2(o0, o1);
                }
            }
        }
    }
}

// --------------------------- attention (per window) -------------------------
__global__ void __launch_bounds__(256)
attn_kernel(const __half* __restrict__ qkv, __half* __restrict__ o) {
    __shared__ uint32_t qs [16 * 32];
    __shared__ uint32_t ksT[32 * 17];
    __shared__ uint32_t vs [16 * 128];
    __shared__ float    sc [16][17];

    const int w = blockIdx.x, t = threadIdx.x;
    const __half* base = qkv + (size_t)w * 16 * DQKV;

    {
        int which = t >> 7;
        int vi = t & 127;
        int r = vi >> 3, c8 = (vi & 7) * 8;
        uint4 raw = *reinterpret_cast<const uint4*>(base + r * DQKV + which * 64 + c8);
        uint32_t u[4] = {raw.x, raw.y, raw.z, raw.w};
        if (which == 0) {
            #pragma unroll
            for (int p = 0; p < 4; p++) qs[r * 32 + c8 / 2 + p] = u[p];
        } else {
            #pragma unroll
            for (int p = 0; p < 4; p++) ksT[(c8 / 2 + p) * 17 + r] = u[p];
        }
    }
    #pragma unroll
    for (int it = 0; it < 2; it++) {
        int vi = t + it * 256;
        int r = vi >> 5, c8 = (vi & 31) * 8;
        uint4 raw = *reinterpret_cast<const uint4*>(base + r * DQKV + 128 + c8);
        vs[r * 128 + c8 / 2 + 0] = raw.x;
        vs[r * 128 + c8 / 2 + 1] = raw.y;
        vs[r * 128 + c8 / 2 + 2] = raw.z;
        vs[r * 128 + c8 / 2 + 3] = raw.w;
    }
    __syncthreads();

    {
        int qi = t >> 4, kj = t & 15;
        float s = 0.f;
        #pragma unroll
        for (int e2 = 0; e2 < 32; e2++) {
            float2 q = __half22float2(*reinterpret_cast<const __half2*>(&qs[qi * 32 + e2]));
            float2 k = __half22float2(*reinterpret_cast<const __half2*>(&ksT[e2 * 17 + kj]));
            s += q.x * k.x + q.y * k.y;
        }
        sc[qi][kj] = s * 0.125f;
    }
    __syncthreads();

    if (t < 16) {
        float mx = -1e30f;
        #pragma unroll
        for (int j = 0; j < 16; j++) mx = fmaxf(mx, sc[t][j]);
        float sum = 0.f;
        #pragma unroll
        for (int j = 0; j < 16; j++) { float e = __expf(sc[t][j] - mx); sc[t][j] = e; sum += e; }
        float inv = 1.f / sum;
        #pragma unroll
        for (int j = 0; j < 16; j++) sc[t][j] *= inv;
    }
    __syncthreads();

    {
        const int tp  = t >> 5;
        const int cp0 = t & 31;
        float accx[2][4], accy[2][4];
        #pragma unroll
        for (int s = 0; s < 2; s++)
            #pragma unroll
            for (int j = 0; j < 4; j++) { accx[s][j] = 0.f; accy[s][j] = 0.f; }

        #pragma unroll
        for (int kk = 0; kk < 16; kk++) {
            const float a0 = sc[tp][kk];
            const float a1 = sc[tp + 8][kk];
            #pragma unroll
            for (int j = 0; j < 4; j++) {
                float2 v = __half22float2(
                    *reinterpret_cast<const __half2*>(&vs[kk * 128 + cp0 + 32 * j]));
                accx[0][j] += a0 * v.x; accy[0][j] += a0 * v.y;
                accx[1][j] += a1 * v.x; accy[1][j] += a1 * v.y;
            }
        }
        __half* ob0 = o + (size_t)w * 16 * 256 + tp * 256;
        __half* ob1 = ob0 + 8 * 256;
        #pragma unroll
        for (int j = 0; j < 4; j++) {
            const int col = 2 * (cp0 + 32 * j);
            *reinterpret_cast<__half2*>(ob0 + col) = __floats2half2_rn(accx[0][j], accy[0][j]);
            *reinterpret_cast<__half2*>(ob1 + col) = __floats2half2_rn(accx[1][j], accy[1][j]);
        }
    }
}

// ------------------------------ launch --------------------------------------
extern "C" void kernel_launch(void* const* d_in, const int* in_sizes, int n_in,
                              void* d_out, int out_size) {
    const float* x   = (const float*)d_in[0];
    const float* Wq  = (const float*)d_in[1];
    const float* bq  = (const float*)d_in[2];
    const float* Wk  = (const float*)d_in[3];
    const float* bk  = (const float*)d_in[4];
    const float* Wv  = (const float*)d_in[5];
    const float* bv  = (const float*)d_in[6];
    const float* Wo  = (const float*)d_in[7];
    const float* bo  = (const float*)d_in[8];
    const float* g1  = (const float*)d_in[9];
    const float* b1  = (const float*)d_in[10];
    const float* W1  = (const float*)d_in[11];
    const float* bf1 = (const float*)d_in[12];
    const float* W2  = (const float*)d_in[13];
    const float* bf2 = (const float*)d_in[14];
    const float* g2  = (const float*)d_in[15];
    const float* b2  = (const float*)d_in[16];
    float* out = (float*)d_out;

    void *pxg, *pqkv, *po, *ph, *pf, *pbtq, *pbto, *pbt1, *pbt2, *pbq;
    cudaGetSymbolAddress(&pxg, g_xg);
    cudaGetSymbolAddress(&pqkv, g_qkv);
    cudaGetSymbolAddress(&po,  g_o);
    cudaGetSymbolAddress(&ph,  g_h);
    cudaGetSymbolAddress(&pf,  g_f);
    cudaGetSymbolAddress(&pbtq, g_bt_qkv);
    cudaGetSymbolAddress(&pbto, g_bt_o);
    cudaGetSymbolAddress(&pbt1, g_bt_1);
    cudaGetSymbolAddress(&pbt2, g_bt_2);
    cudaGetSymbolAddress(&pbq,  g_bqkv);
    __half* xg = (__half*)pxg; __half* qkv = (__half*)pqkv; __half* o = (__half*)po;
    __half* h = (__half*)ph; __half* f = (__half*)pf;
    __half* btq = (__half*)pbtq; __half* bto = (__half*)pbto;
    __half* bt1 = (__half*)pbt1; __half* bt2 = (__half*)pbt2;
    float* bqkv = (float*)pbq;

    cudaFuncSetAttribute(gemm_bc<false>, cudaFuncAttributeMaxDynamicSharedMemorySize, BC_SMEM);
    cudaFuncSetAttribute(gemm_bc<true >, cudaFuncAttributeMaxDynamicSharedMemorySize, BC_SMEM);
    cudaFuncSetAttribute(gemm_ln<256,  false, __half>, cudaFuncAttributeMaxDynamicSharedMemorySize, GL_SMEM);
    cudaFuncSetAttribute(gemm_ln<1024, true,  float >, cudaFuncAttributeMaxDynamicSharedMemorySize, GL_SMEM);

    wtrans_all<<<2688, 256>>>(Wq, Wk, Wv, Wo, W1, W2, btq, bto, bt1, bt2);
    prof_pad<<<1, 32>>>(xg);   // keeps profiler slot on gemm_bc (QKV)

    cudaMemcpyAsync(bqkv,       bq, 64  * sizeof(float), cudaMemcpyDeviceToDevice);
    cudaMemcpyAsync(bqkv + 64,  bk, 64  * sizeof(float), cudaMemcpyDeviceToDevice);
    cudaMemcpyAsync(bqkv + 128, bv, 256 * sizeof(float), cudaMemcpyDeviceToDevice);

    const int MB4 = M_TOK / (128 * BC_MT);   // 256

    gather_kernel<<<NWIN, 256>>>(x, xg);

    // qkv = xg @ [Wq|Wk|Wv]^T + b            (profiled launch)
    gemm_bc<false><<<dim3(3, MB4), 256, BC_SMEM>>>(xg, btq, bqkv, qkv, DQKV);

    attn_kernel<<<NWIN, 256>>>(qkv, o);

    // h = LN(xg + o @ Wo + bo)   (fused)
    gemm_ln<256, false, __half><<<M_TOK / 128, 512, GL_SMEM>>>(
        o, bto, bo, xg, g1, b1, h);

    // f = relu(h @ W1 + bf1)
    gemm_bc<true ><<<dim3(8, MB4), 256, BC_SMEM>>>(h, bt1, bf1, f, DFF);

    // out = scatter(LN(h + f @ W2 + bf2))   (fused)
    gemm_ln<1024, true, float><<<M_TOK / 128, 512, GL_SMEM>>>(
        f, bt2, bf2, h, g2, b2, out);
}